// round 10
// baseline (speedup 1.0000x reference)
#include <cuda_runtime.h>
#include <cuda_fp16.h>
#include <cstdint>

// ---------------- static problem constants ----------------
#define HH 495
#define WW 436
#define NN (HH*WW)            // 215820 nodes
#define PRR 248
#define PCC 218
#define NP (PRR*PCC)          // 54064 pooled nodes
#define E_NS ((HH-1)*WW)      // 215384 edges (north & south)
#define E_EW (HH*(WW-1))      // 215325 edges (east & west)
#define M_NS (247*218)
#define M_EW (248*217)

// output layout (float elements)
#define OFF_POS 6920192
#define OFF_EIN 7028320
#define OFF_EIE 7136012
#define OFF_EIS 7243644
#define OFF_EIW 7351336
#define OFF_FN  7458968
#define OFF_FE  9182040
#define OFF_FS  10904152
#define OFF_FW  12627224
#define OUT_TOTAL 14349336

// ---------------- scratch ----------------
__device__ __align__(16) __half g_XQ[(size_t)NN*128];     // fp16
__device__ __align__(16) __half g_EDGEH[4][(size_t)E_NS*32]; // fp16 edge MLP outputs
// fp16 weight images, [chunk][128n][64k], 128B rows, swizzled
__device__ __align__(16) __half g_B1[2][128*64];
__device__ __align__(16) __half g_B2[4][128*64];
// edge weights: 128-k rows (256B), K padded 96->128
__device__ __align__(16) __half g_BE[4][32*128];

// ---------------- helpers ----------------
__device__ __forceinline__ uint32_t smem_u32(const void* p){
    uint32_t a;
    asm("{ .reg .u64 t; cvta.to.shared.u64 t, %1; cvt.u32.u64 %0, t; }" : "=r"(a) : "l"(p));
    return a;
}
__device__ __forceinline__ uint32_t swoff64(int row, int k){
    return (uint32_t)(row * 128 + (((k >> 3) ^ (row & 7)) << 4) + (k & 7) * 2);
}
__device__ __forceinline__ uint32_t swoff256(int row, int k){
    return (uint32_t)(row * 256 + (((k >> 3) ^ (row & 7)) << 4) + (k & 7) * 2);
}
__device__ __forceinline__ uint32_t pk_h2(float a, float b){
    __half2 h = __floats2half2_rn(a, b);
    return *reinterpret_cast<uint32_t*>(&h);
}

#define LDSM_X4(r0,r1,r2,r3,addr) \
    asm volatile("ldmatrix.sync.aligned.m8n8.x4.shared.b16 {%0,%1,%2,%3}, [%4];" \
        : "=r"(r0), "=r"(r1), "=r"(r2), "=r"(r3) : "r"(addr))

__device__ __forceinline__ void mma_f16(float* c, const uint32_t* a, uint32_t b0, uint32_t b1){
    asm volatile(
        "mma.sync.aligned.m16n8k16.row.col.f32.f16.f16.f32 "
        "{%0,%1,%2,%3}, {%4,%5,%6,%7}, {%8,%9}, {%0,%1,%2,%3};"
        : "+f"(c[0]), "+f"(c[1]), "+f"(c[2]), "+f"(c[3])
        : "r"(a[0]), "r"(a[1]), "r"(a[2]), "r"(a[3]), "r"(b0), "r"(b1));
}

#define CP16(dst, src) asm volatile("cp.async.cg.shared.global [%0], [%1], 16;" :: "r"(dst), "l"(src))
#define CP_COMMIT()    asm volatile("cp.async.commit_group;" ::: "memory")
#define CP_WAIT0()     asm volatile("cp.async.wait_group 0;" ::: "memory")
#define CP_WAIT1()     asm volatile("cp.async.wait_group 1;" ::: "memory")

// smem layout node GEMMs: A double buffer + B triple ring
#define SOF_A0 0
#define SOF_A1 16384
#define SOF_B  32768            // + 16384*i, i=0..2
#define SMEM_TG 81920
// edge GEMM: 256-edge tile
#define EOF_A 0                 // 64KB (256 x 128 fp16, 256B rows)
#define EOF_B 65536             // 8KB
#define SMEM_TE 73728

// ---------------- weight preconversion ----------------
__global__ void k_conv_w(const float* __restrict__ Wemb, const float* __restrict__ Wnode,
                         const float* __restrict__ Wedge){
    int t = blockIdx.x * 256 + threadIdx.x;
    if (t < 16384){   // B1: [2][128n][64k]
        int n = t >> 7, kg = t & 127;
        int c = kg >> 6, k = kg & 63;
        float w = Wemb[(n >> 5) * 4096 + kg * 32 + (n & 31)];
        *(__half*)((char*)g_B1 + (uint32_t)c * 16384 + swoff64(n, k)) = __float2half_rn(w);
        return;
    }
    t -= 16384;
    if (t < 32768){   // B2: [4][128n][64k]
        int n = t >> 8, kg = t & 255;
        int c = kg >> 6, k = kg & 63;
        float w = Wnode[kg * 128 + n];
        if (kg >= 128) w *= 0.25f;
        *(__half*)((char*)g_B2 + (uint32_t)c * 16384 + swoff64(n, k)) = __float2half_rn(w);
        return;
    }
    t -= 32768;
    if (t < 16384){   // edge weights: [4][32n][128k], zero-padded k>=96
        int q = t >> 12, r = t & 4095;
        int n = r >> 7, k = r & 127;
        float w = (k < 96) ? Wedge[q * 3072 + k * 32 + n] : 0.f;
        *(__half*)((char*)g_BE[q] + swoff256(n, k)) = __float2half_rn(w);
    }
}

// zero the pooled-output region (atomicMax target)
__global__ void k_init(float* __restrict__ out){
    int t = blockIdx.x * 256 + threadIdx.x;
    if (t < NP * 32) ((float4*)out)[t] = make_float4(0.f, 0.f, 0.f, 0.f);
}

// ---------------- single-pass fp16 MMA over one 64-K chunk (warp tile 32x32) ----------------
__device__ __forceinline__ void mma_chunk64(uint32_t Ab, uint32_t Bb,
                                            int warp_m, int warp_n, int lane, float acc[2][4][4]){
#pragma unroll
    for (int kc = 0; kc < 4; kc++){
        uint32_t a[2][4];
#pragma unroll
        for (int tf = 0; tf < 2; tf++){
            int row = warp_m * 32 + tf * 16 + (lane & 15);
            int ch = kc * 2 + (lane >> 4);
            uint32_t off = row * 128 + ((ch ^ (row & 7)) << 4);
            LDSM_X4(a[tf][0], a[tf][1], a[tf][2], a[tf][3], Ab + off);
        }
        uint32_t bfr[4][2];
#pragma unroll
        for (int jj = 0; jj < 2; jj++){
            int rowN = warp_n * 32 + jj * 16 + (lane & 7) + ((lane >> 4) << 3);
            int ch = kc * 2 + ((lane >> 3) & 1);
            uint32_t off = rowN * 128 + ((ch ^ (rowN & 7)) << 4);
            uint32_t r0, r1, r2, r3;
            LDSM_X4(r0, r1, r2, r3, Bb + off);
            bfr[jj*2][0] = r0;   bfr[jj*2][1] = r1;
            bfr[jj*2+1][0] = r2; bfr[jj*2+1][1] = r3;
        }
#pragma unroll
        for (int tf = 0; tf < 2; tf++)
#pragma unroll
            for (int j = 0; j < 4; j++)
                mma_f16(acc[tf][j], a[tf], bfr[j][0], bfr[j][1]);
    }
}

// fp32 regs -> fp16 swizzled smem A buffer
__device__ __forceinline__ void sts_a(char* smem, uint32_t abase, const float4 v[4], int m, int k16){
    uint4 H0, H1;
    H0.x = pk_h2(v[0].x, v[0].y); H0.y = pk_h2(v[0].z, v[0].w);
    H0.z = pk_h2(v[1].x, v[1].y); H0.w = pk_h2(v[1].z, v[1].w);
    H1.x = pk_h2(v[2].x, v[2].y); H1.y = pk_h2(v[2].z, v[2].w);
    H1.z = pk_h2(v[3].x, v[3].y); H1.w = pk_h2(v[3].z, v[3].w);
    *(uint4*)(smem + abase + swoff64(m, k16))     = H0;
    *(uint4*)(smem + abase + swoff64(m, k16 + 8)) = H1;
}
// fp16 regs -> smem
__device__ __forceinline__ void sts_a16(char* smem, uint32_t abase, const uint4 hv[2], int m, int k16){
    *(uint4*)(smem + abase + swoff64(m, k16))     = hv[0];
    *(uint4*)(smem + abase + swoff64(m, k16 + 8)) = hv[1];
}

__device__ __forceinline__ void cp_b(uint32_t sbuf, const char* src, int tid){
#pragma unroll
    for (int i = 0; i < 2; i++){
        uint32_t o = (uint32_t)(tid + 512 * i) * 16;
        CP16(sbuf + o, src + o);
    }
    CP_COMMIT();
}

// A-chunk loaders (thread: row gm, 16 values at k16)
__device__ __forceinline__ void ldg_a_x(const float* __restrict__ x, int gm, int c, int k16, float4 v[4]){
    v[0] = v[1] = v[2] = v[3] = make_float4(0.f,0.f,0.f,0.f);
    if (gm < NN){
        const float* src = x + (size_t)gm * 128 + c * 64 + k16;
        v[0] = *(const float4*)(src);
        v[1] = *(const float4*)(src + 4);
        v[2] = *(const float4*)(src + 8);
        v[3] = *(const float4*)(src + 12);
    }
}
__device__ __forceinline__ void ldg_a_agg16(int gm, int c, int k16, uint4 hv[2]){
    hv[0] = make_uint4(0u,0u,0u,0u); hv[1] = hv[0];
    if (gm < NN){
        int d = (c - 2) * 2 + (k16 >> 5);
        int u = k16 & 31;
        int r = gm / WW, cc = gm - r * WW;
        int e = -1;
        if (d == 0){ if (r < HH-1) e = gm; }
        else if (d == 1){ if (cc >= 1) e = r*(WW-1) + cc - 1; }
        else if (d == 2){ if (r >= 1) e = gm - WW; }
        else            { if (cc <= WW-2) e = r*(WW-1) + cc; }
        if (e >= 0){
            const uint4* src = (const uint4*)(&g_EDGEH[d][0] + (size_t)e * 32 + u);
            hv[0] = src[0];
            hv[1] = src[1];
        }
    }
}

// ---------------- GEMM1: XQ(fp16) = relu(x @ Wcat), C=2 chunks ----------------
__global__ __launch_bounds__(512, 1) void k_tg1(const float* __restrict__ x){
    extern __shared__ char smem[];
    const uint32_t sb = smem_u32(smem);
    const int tid = threadIdx.x, wid = tid >> 5, lane = tid & 31;
    const int warp_m = wid >> 2, warp_n = wid & 3;
    const int M0 = blockIdx.x * 128;
    const int m = tid >> 2, k16 = (tid & 3) * 16, gm = M0 + m;

    float acc[2][4][4];
#pragma unroll
    for (int t = 0; t < 2; t++)
#pragma unroll
        for (int j = 0; j < 4; j++)
#pragma unroll
            for (int e = 0; e < 4; e++) acc[t][j][e] = 0.f;

    float4 v[4];
    cp_b(sb + SOF_B, (const char*)g_B1, tid);
    ldg_a_x(x, gm, 0, k16, v);

#pragma unroll
    for (int c = 0; c < 2; c++){
        uint32_t abase = (c & 1) ? SOF_A1 : SOF_A0;
        sts_a(smem, abase, v, m, k16);
        if (c == 0){
            cp_b(sb + SOF_B + 16384, (const char*)g_B1 + 16384, tid);
            ldg_a_x(x, gm, 1, k16, v);
            CP_WAIT1();
        } else {
            CP_WAIT0();
        }
        __syncthreads();
        mma_chunk64(sb + abase, sb + SOF_B + (c % 3) * 16384, warp_m, warp_n, lane, acc);
    }
#pragma unroll
    for (int tf = 0; tf < 2; tf++){
        int r0 = M0 + warp_m * 32 + tf * 16 + (lane >> 2);
#pragma unroll
        for (int j = 0; j < 4; j++){
            int col = warp_n * 32 + j * 8 + (lane & 3) * 2;
            if (r0 < NN)
                *(uint32_t*)(g_XQ + (size_t)r0 * 128 + col) =
                    pk_h2(fmaxf(acc[tf][j][0], 0.f), fmaxf(acc[tf][j][1], 0.f));
            if (r0 + 8 < NN)
                *(uint32_t*)(g_XQ + (size_t)(r0 + 8) * 128 + col) =
                    pk_h2(fmaxf(acc[tf][j][2], 0.f), fmaxf(acc[tf][j][3], 0.f));
        }
    }
}

// ---------------- GEMM2 + fused 2x2 pooling, C=4 chunks ----------------
__global__ __launch_bounds__(512, 1) void k_tg2(const float* __restrict__ x,
                                                float* __restrict__ out){
    extern __shared__ char smem[];
    const uint32_t sb = smem_u32(smem);
    const int tid = threadIdx.x, wid = tid >> 5, lane = tid & 31;
    const int warp_m = wid >> 2, warp_n = wid & 3;
    const int M0 = blockIdx.x * 128;
    const int m = tid >> 2, k16 = (tid & 3) * 16, gm = M0 + m;

    float acc[2][4][4];
#pragma unroll
    for (int t = 0; t < 2; t++)
#pragma unroll
        for (int j = 0; j < 4; j++)
#pragma unroll
            for (int e = 0; e < 4; e++) acc[t][j][e] = 0.f;

    float4 v[4];
    uint4 hv[2];
    cp_b(sb + SOF_B, (const char*)g_B2, tid);
    ldg_a_x(x, gm, 0, k16, v);

#pragma unroll
    for (int c = 0; c < 4; c++){
        uint32_t abase = (c & 1) ? SOF_A1 : SOF_A0;
        if (c < 2) sts_a(smem, abase, v, m, k16);
        else       sts_a16(smem, abase, hv, m, k16);
        if (c < 3){
            cp_b(sb + SOF_B + ((c + 1) % 3) * 16384,
                 (const char*)g_B2 + (size_t)(c + 1) * 16384, tid);
            if (c + 1 < 2) ldg_a_x(x, gm, c + 1, k16, v);
            else           ldg_a_agg16(gm, c + 1, k16, hv);
            CP_WAIT1();
        } else {
            CP_WAIT0();
        }
        __syncthreads();
        mma_chunk64(sb + abase, sb + SOF_B + (c % 3) * 16384, warp_m, warp_n, lane, acc);
    }

    // fused pooling epilogue: relu -> horizontal pair max via shuffle -> atomicMax
#pragma unroll
    for (int tf = 0; tf < 2; tf++){
#pragma unroll
        for (int half = 0; half < 2; half++){
            int r = M0 + warp_m * 32 + tf * 16 + (lane >> 2) + half * 8;
#pragma unroll
            for (int j = 0; j < 4; j++){
                float v0 = fmaxf(acc[tf][j][half*2 + 0], 0.f);
                float v1 = fmaxf(acc[tf][j][half*2 + 1], 0.f);
                float m0 = fmaxf(v0, __shfl_xor_sync(0xffffffffu, v0, 4));
                float m1 = fmaxf(v1, __shfl_xor_sync(0xffffffffu, v1, 4));
                if ((((lane >> 2) & 1) == 0) && r < NN){
                    int gr = r / WW, gc = r - gr * WW;
                    int p = (gr >> 1) * PCC + (gc >> 1);
                    int col = warp_n * 32 + j * 8 + (lane & 3) * 2;
                    atomicMax((int*)(out + (size_t)p * 128 + col),     __float_as_int(m0));
                    atomicMax((int*)(out + (size_t)p * 128 + col + 1), __float_as_int(m1));
                }
            }
        }
    }
}

// =====================================================================
// Edge GEMM: 256-edge tile, 1 thread fills 1 edge row; fp16 output
// warp tile 32 edges x 32 n; K=96 (6 kc)
// =====================================================================
__global__ __launch_bounds__(256, 3) void k_edge(const float* __restrict__ efN,
                                                 const float* __restrict__ efE,
                                                 const float* __restrict__ efS,
                                                 const float* __restrict__ efW,
                                                 int unused){
    extern __shared__ char smem[];
    const uint32_t sb = smem_u32(smem);
    const int q = blockIdx.y;
    const float* ef = (q==0) ? efN : (q==1) ? efE : (q==2) ? efS : efW;
    const int E = (q==0 || q==2) ? E_NS : E_EW;
    const int M0 = blockIdx.x * 256;
    if (M0 >= E) return;
    const int tid = threadIdx.x, wid = tid >> 5, lane = tid & 31;

    // B copy (8KB)
    {
        const uint4* bh = (const uint4*)g_BE[q];
#pragma unroll
        for (int i = 0; i < 2; i++){
            int idx = tid + 256 * i;
            ((uint4*)(smem + EOF_B))[idx] = bh[idx];
        }
    }
    // A fill: thread owns edge e = M0 + tid, all 12 16B-chunks
    {
        int e = M0 + tid;
        if (e < E){
            int s, t;
            if (q == 0){ s = e + WW; t = e; }
            else if (q == 2){ s = e; t = e + WW; }
            else { int r = e / (WW - 1); if (q == 1){ s = e + r; t = s + 1; } else { t = e + r; s = t + 1; } }
            // ef: 32 fp32 -> 4 fp16 chunks
            const float4* efp = (const float4*)(ef + (size_t)e * 32);
#pragma unroll
            for (int c = 0; c < 4; c++){
                float4 v0 = efp[2*c], v1 = efp[2*c+1];
                uint4 H;
                H.x = pk_h2(v0.x, v0.y); H.y = pk_h2(v0.z, v0.w);
                H.z = pk_h2(v1.x, v1.y); H.w = pk_h2(v1.z, v1.w);
                *(uint4*)(smem + EOF_A + swoff256(tid, c * 8)) = H;
            }
            const uint4* sp = (const uint4*)(g_XQ + (size_t)s * 128 + q * 32);
            const uint4* tp = (const uint4*)(g_XQ + (size_t)t * 128 + q * 32);
#pragma unroll
            for (int c = 0; c < 4; c++)
                *(uint4*)(smem + EOF_A + swoff256(tid, 32 + c * 8)) = sp[c];
#pragma unroll
            for (int c = 0; c < 4; c++)
                *(uint4*)(smem + EOF_A + swoff256(tid, 64 + c * 8)) = tp[c];
        } else {
            uint4 Z = make_uint4(0u,0u,0u,0u);
#pragma unroll
            for (int c = 0; c < 12; c++)
                *(uint4*)(smem + EOF_A + swoff256(tid, c * 8)) = Z;
        }
    }
    __syncthreads();

    float acc[2][4][4];
#pragma unroll
    for (int t = 0; t < 2; t++)
#pragma unroll
        for (int j = 0; j < 4; j++)
#pragma unroll
            for (int e = 0; e < 4; e++) acc[t][j][e] = 0.f;

#pragma unroll
    for (int kc = 0; kc < 6; kc++){
        uint32_t a[2][4];
#pragma unroll
        for (int tf = 0; tf < 2; tf++){
            int row = wid * 32 + tf * 16 + (lane & 15);
            int ch = kc * 2 + (lane >> 4);
            uint32_t off = row * 256 + ((ch ^ (row & 7)) << 4);
            LDSM_X4(a[tf][0], a[tf][1], a[tf][2], a[tf][3], sb + EOF_A + off);
        }
        uint32_t bfr[4][2];
#pragma unroll
        for (int jj = 0; jj < 2; jj++){
            int rowN = jj * 16 + (lane & 7) + ((lane >> 4) << 3);
            int ch = kc * 2 + ((lane >> 3) & 1);
            uint32_t off = rowN * 256 + ((ch ^ (rowN & 7)) << 4);
            uint32_t r0, r1, r2, r3;
            LDSM_X4(r0, r1, r2, r3, sb + EOF_B + off);
            bfr[jj*2][0] = r0;   bfr[jj*2][1] = r1;
            bfr[jj*2+1][0] = r2; bfr[jj*2+1][1] = r3;
        }
#pragma unroll
        for (int tf = 0; tf < 2; tf++)
#pragma unroll
            for (int j = 0; j < 4; j++)
                mma_f16(acc[tf][j], a[tf], bfr[j][0], bfr[j][1]);
    }

    __half* ED = &g_EDGEH[q][0];
#pragma unroll
    for (int tf = 0; tf < 2; tf++){
        int r0 = M0 + wid * 32 + tf * 16 + (lane >> 2);
#pragma unroll
        for (int j = 0; j < 4; j++){
            int col = j * 8 + (lane & 3) * 2;
            if (r0 < E)
                *(uint32_t*)(ED + (size_t)r0 * 32 + col) =
                    pk_h2(fmaxf(acc[tf][j][0], 0.f), fmaxf(acc[tf][j][1], 0.f));
            if (r0 + 8 < E)
                *(uint32_t*)(ED + (size_t)(r0 + 8) * 32 + col) =
                    pk_h2(fmaxf(acc[tf][j][2], 0.f), fmaxf(acc[tf][j][3], 0.f));
        }
    }
}

// ---------------- metadata / edge-feature kernels ----------------
__global__ void k_meta(float* __restrict__ out){
    int t = blockIdx.x * 256 + threadIdx.x;
    if (t < NP){
        out[OFF_POS + 2*t]     = (float)(t / PCC);
        out[OFF_POS + 2*t + 1] = (float)(t % PCC);
        return;
    }
    t -= NP;
    if (t < M_NS){
        int k = 1 + t / PCC, j = t % PCC;
        out[OFF_EIN + 2*t]     = (float)(k*PCC + j);
        out[OFF_EIN + 2*t + 1] = (float)((k-1)*PCC + j);
        return;
    }
    t -= M_NS;
    if (t < M_EW){
        int k = t / 217, j = t % 217;
        int s = k*PCC + j;
        out[OFF_EIE + 2*t]     = (float)s;
        out[OFF_EIE + 2*t + 1] = (float)(s + 1);
        return;
    }
    t -= M_EW;
    if (t < M_NS){
        int k = t / PCC, j = t % PCC;
        int s = k*PCC + j;
        out[OFF_EIS + 2*t]     = (float)s;
        out[OFF_EIS + 2*t + 1] = (float)(s + PCC);
        return;
    }
    t -= M_NS;
    if (t < M_EW){
        int k = t / 217, j = t % 217 + 1;
        int s = k*PCC + j;
        out[OFF_EIW + 2*t]     = (float)s;
        out[OFF_EIW + 2*t + 1] = (float)(s - 1);
        return;
    }
}

__global__ void k_efeat(float* __restrict__ out){
    const int d = blockIdx.y;
    const int M = (d == 0 || d == 2) ? M_NS : M_EW;
    int t = blockIdx.x * 256 + threadIdx.x;
    if (t >= M * 4) return;
    int m = t >> 2, fi = (t & 3) * 8;   // 8 halves = 16B per thread
    int e1, stride2 = 1; bool two = true; size_t off;
    if (d == 0){      int k = 1 + m/PCC, j = m%PCC; e1 = (2*k - 1)*WW + 2*j;      off = OFF_FN; }
    else if (d == 1){ int k = m/217,     j = m%217; e1 = 2*k*(WW-1) + 2*j + 1;    stride2 = WW-1; two = (k < 247); off = OFF_FE; }
    else if (d == 2){ int k = m/PCC,     j = m%PCC; e1 = (2*k + 1)*WW + 2*j;      off = OFF_FS; }
    else {            int k = m/217,     j = m%217 + 1; e1 = 2*k*(WW-1) + 2*j - 1; stride2 = WW-1; two = (k < 247); off = OFF_FW; }
    const __half* ED = &g_EDGEH[d][0];
    uint4 A = *(const uint4*)(ED + (size_t)e1*32 + fi);
    uint4 B = two ? *(const uint4*)(ED + (size_t)(e1 + stride2)*32 + fi) : make_uint4(0u,0u,0u,0u);
    float* o = out + off + (size_t)m*32 + fi;
    const uint32_t* aw = &A.x;
    const uint32_t* bw = &B.x;
#pragma unroll
    for (int w = 0; w < 4; w++){
        float2 fa = __half22float2(*(const __half2*)&aw[w]);
        float2 fb = __half22float2(*(const __half2*)&bw[w]);
        o[2*w]   = fmaxf(fa.x, fb.x);
        o[2*w+1] = fmaxf(fa.y, fb.y);
    }
}

// =====================================================================
extern "C" void kernel_launch(void* const* d_in, const int* in_sizes, int n_in,
                              void* d_out, int out_size){
    const float* x     = (const float*)d_in[0];
    const float* efN   = (const float*)d_in[6];
    const float* efE   = (const float*)d_in[7];
    const float* efS   = (const float*)d_in[8];
    const float* efW   = (const float*)d_in[9];
    const float* Wemb  = (const float*)d_in[10];
    const float* Wedge = (const float*)d_in[11];
    const float* Wnode = (const float*)d_in[12];
    float* out = (float*)d_out;

    static bool attr_done = false;
    if (!attr_done){
        cudaFuncSetAttribute(k_tg1, cudaFuncAttributeMaxDynamicSharedMemorySize, SMEM_TG);
        cudaFuncSetAttribute(k_tg2, cudaFuncAttributeMaxDynamicSharedMemorySize, SMEM_TG);
        cudaFuncSetAttribute(k_edge, cudaFuncAttributeMaxDynamicSharedMemorySize, SMEM_TE);
        attr_done = true;
    }

    const int gm = (NN + 127) / 128;             // 1687 tiles
    k_conv_w<<<(65536 + 255)/256, 256>>>(Wemb, Wnode, Wedge);
    k_init<<<(NP*32 + 255)/256, 256>>>(out);
    k_tg1<<<gm, 512, SMEM_TG>>>(x);
    dim3 ge((E_NS + 255) / 256, 4);
    k_edge<<<ge, 256, SMEM_TE>>>(efN, efE, efS, efW, 0);
    k_tg2<<<gm, 512, SMEM_TG>>>(x, out);

    const int metaT = NP + 2*M_NS + 2*M_EW;
    dim3 gf((M_NS*4 + 255) / 256, 4);
    k_meta<<<(metaT + 255)/256, 256>>>(out);
    k_efeat<<<gf, 256>>>(out);
}

// round 11
// speedup vs baseline: 1.0338x; 1.0338x over previous
#include <cuda_runtime.h>
#include <cuda_fp16.h>
#include <cstdint>

// ---------------- static problem constants ----------------
#define HH 495
#define WW 436
#define NN (HH*WW)            // 215820 nodes
#define PRR 248
#define PCC 218
#define NP (PRR*PCC)          // 54064 pooled nodes
#define E_NS ((HH-1)*WW)      // 215384 edges (north & south)
#define E_EW (HH*(WW-1))      // 215325 edges (east & west)
#define M_NS (247*218)
#define M_EW (248*217)

// output layout (float elements)
#define OFF_POS 6920192
#define OFF_EIN 7028320
#define OFF_EIE 7136012
#define OFF_EIS 7243644
#define OFF_EIW 7351336
#define OFF_FN  7458968
#define OFF_FE  9182040
#define OFF_FS  10904152
#define OFF_FW  12627224
#define OUT_TOTAL 14349336

// ---------------- scratch ----------------
__device__ __align__(16) __half g_XQ[(size_t)NN*128];        // fp16
__device__ __align__(16) __half g_EDGEH[4][(size_t)E_NS*32]; // fp16 edge MLP outputs
// fp16 weight images, [chunk][128n][64k], 128B rows, swizzled
__device__ __align__(16) __half g_B1[2][128*64];
__device__ __align__(16) __half g_B2[4][128*64];
// edge weights: 128-k rows (256B), K padded 96->128
__device__ __align__(16) __half g_BE[4][32*128];

// ---------------- helpers ----------------
__device__ __forceinline__ uint32_t smem_u32(const void* p){
    uint32_t a;
    asm("{ .reg .u64 t; cvta.to.shared.u64 t, %1; cvt.u32.u64 %0, t; }" : "=r"(a) : "l"(p));
    return a;
}
__device__ __forceinline__ uint32_t swoff64(int row, int k){
    return (uint32_t)(row * 128 + (((k >> 3) ^ (row & 7)) << 4) + (k & 7) * 2);
}
__device__ __forceinline__ uint32_t swoff256(int row, int k){
    return (uint32_t)(row * 256 + (((k >> 3) ^ (row & 7)) << 4) + (k & 7) * 2);
}
__device__ __forceinline__ uint32_t pk_h2(float a, float b){
    __half2 h = __floats2half2_rn(a, b);
    return *reinterpret_cast<uint32_t*>(&h);
}

#define LDSM_X4(r0,r1,r2,r3,addr) \
    asm volatile("ldmatrix.sync.aligned.m8n8.x4.shared.b16 {%0,%1,%2,%3}, [%4];" \
        : "=r"(r0), "=r"(r1), "=r"(r2), "=r"(r3) : "r"(addr))

__device__ __forceinline__ void mma_f16(float* c, const uint32_t* a, uint32_t b0, uint32_t b1){
    asm volatile(
        "mma.sync.aligned.m16n8k16.row.col.f32.f16.f16.f32 "
        "{%0,%1,%2,%3}, {%4,%5,%6,%7}, {%8,%9}, {%0,%1,%2,%3};"
        : "+f"(c[0]), "+f"(c[1]), "+f"(c[2]), "+f"(c[3])
        : "r"(a[0]), "r"(a[1]), "r"(a[2]), "r"(a[3]), "r"(b0), "r"(b1));
}

#define CP16(dst, src) asm volatile("cp.async.cg.shared.global [%0], [%1], 16;" :: "r"(dst), "l"(src))
#define CP_COMMIT()    asm volatile("cp.async.commit_group;" ::: "memory")
#define CP_WAIT0()     asm volatile("cp.async.wait_group 0;" ::: "memory")
#define CP_WAIT1()     asm volatile("cp.async.wait_group 1;" ::: "memory")

// smem layout node GEMMs: A double buffer + B triple ring
#define SOF_A0 0
#define SOF_A1 16384
#define SOF_B  32768            // + 16384*i, i=0..2
#define SMEM_TG 81920
// edge GEMM: 128-edge tile (R9 structure)
#define EOF_A 0                 // 32KB (128 x 128 fp16, 256B rows)
#define EOF_B 32768             // 8KB
#define SMEM_TE 40960

// ---------------- weight preconversion ----------------
__global__ void k_conv_w(const float* __restrict__ Wemb, const float* __restrict__ Wnode,
                         const float* __restrict__ Wedge){
    int t = blockIdx.x * 256 + threadIdx.x;
    if (t < 16384){   // B1: [2][128n][64k]
        int n = t >> 7, kg = t & 127;
        int c = kg >> 6, k = kg & 63;
        float w = Wemb[(n >> 5) * 4096 + kg * 32 + (n & 31)];
        *(__half*)((char*)g_B1 + (uint32_t)c * 16384 + swoff64(n, k)) = __float2half_rn(w);
        return;
    }
    t -= 16384;
    if (t < 32768){   // B2: [4][128n][64k]
        int n = t >> 8, kg = t & 255;
        int c = kg >> 6, k = kg & 63;
        float w = Wnode[kg * 128 + n];
        if (kg >= 128) w *= 0.25f;
        *(__half*)((char*)g_B2 + (uint32_t)c * 16384 + swoff64(n, k)) = __float2half_rn(w);
        return;
    }
    t -= 32768;
    if (t < 16384){   // edge weights: [4][32n][128k], zero-padded k>=96
        int q = t >> 12, r = t & 4095;
        int n = r >> 7, k = r & 127;
        float w = (k < 96) ? Wedge[q * 3072 + k * 32 + n] : 0.f;
        *(__half*)((char*)g_BE[q] + swoff256(n, k)) = __float2half_rn(w);
    }
}

// zero the pooled-output region (atomicMax target)
__global__ void k_init(float* __restrict__ out){
    int t = blockIdx.x * 256 + threadIdx.x;
    if (t < NP * 32) ((float4*)out)[t] = make_float4(0.f, 0.f, 0.f, 0.f);
}

// ---------------- single-pass fp16 MMA over one 64-K chunk (warp tile 32x32) ----------------
__device__ __forceinline__ void mma_chunk64(uint32_t Ab, uint32_t Bb,
                                            int warp_m, int warp_n, int lane, float acc[2][4][4]){
#pragma unroll
    for (int kc = 0; kc < 4; kc++){
        uint32_t a[2][4];
#pragma unroll
        for (int tf = 0; tf < 2; tf++){
            int row = warp_m * 32 + tf * 16 + (lane & 15);
            int ch = kc * 2 + (lane >> 4);
            uint32_t off = row * 128 + ((ch ^ (row & 7)) << 4);
            LDSM_X4(a[tf][0], a[tf][1], a[tf][2], a[tf][3], Ab + off);
        }
        uint32_t bfr[4][2];
#pragma unroll
        for (int jj = 0; jj < 2; jj++){
            int rowN = warp_n * 32 + jj * 16 + (lane & 7) + ((lane >> 4) << 3);
            int ch = kc * 2 + ((lane >> 3) & 1);
            uint32_t off = rowN * 128 + ((ch ^ (rowN & 7)) << 4);
            uint32_t r0, r1, r2, r3;
            LDSM_X4(r0, r1, r2, r3, Bb + off);
            bfr[jj*2][0] = r0;   bfr[jj*2][1] = r1;
            bfr[jj*2+1][0] = r2; bfr[jj*2+1][1] = r3;
        }
#pragma unroll
        for (int tf = 0; tf < 2; tf++)
#pragma unroll
            for (int j = 0; j < 4; j++)
                mma_f16(acc[tf][j], a[tf], bfr[j][0], bfr[j][1]);
    }
}

// fp32 regs -> fp16 swizzled smem A buffer
__device__ __forceinline__ void sts_a(char* smem, uint32_t abase, const float4 v[4], int m, int k16){
    uint4 H0, H1;
    H0.x = pk_h2(v[0].x, v[0].y); H0.y = pk_h2(v[0].z, v[0].w);
    H0.z = pk_h2(v[1].x, v[1].y); H0.w = pk_h2(v[1].z, v[1].w);
    H1.x = pk_h2(v[2].x, v[2].y); H1.y = pk_h2(v[2].z, v[2].w);
    H1.z = pk_h2(v[3].x, v[3].y); H1.w = pk_h2(v[3].z, v[3].w);
    *(uint4*)(smem + abase + swoff64(m, k16))     = H0;
    *(uint4*)(smem + abase + swoff64(m, k16 + 8)) = H1;
}
// fp16 regs -> smem
__device__ __forceinline__ void sts_a16(char* smem, uint32_t abase, const uint4 hv[2], int m, int k16){
    *(uint4*)(smem + abase + swoff64(m, k16))     = hv[0];
    *(uint4*)(smem + abase + swoff64(m, k16 + 8)) = hv[1];
}

__device__ __forceinline__ void cp_b(uint32_t sbuf, const char* src, int tid){
#pragma unroll
    for (int i = 0; i < 2; i++){
        uint32_t o = (uint32_t)(tid + 512 * i) * 16;
        CP16(sbuf + o, src + o);
    }
    CP_COMMIT();
}

// A-chunk loaders (thread: row gm, 16 values at k16)
__device__ __forceinline__ void ldg_a_x(const float* __restrict__ x, int gm, int c, int k16, float4 v[4]){
    v[0] = v[1] = v[2] = v[3] = make_float4(0.f,0.f,0.f,0.f);
    if (gm < NN){
        const float* src = x + (size_t)gm * 128 + c * 64 + k16;
        v[0] = *(const float4*)(src);
        v[1] = *(const float4*)(src + 4);
        v[2] = *(const float4*)(src + 8);
        v[3] = *(const float4*)(src + 12);
    }
}
__device__ __forceinline__ void ldg_a_agg16(int gm, int c, int k16, uint4 hv[2]){
    hv[0] = make_uint4(0u,0u,0u,0u); hv[1] = hv[0];
    if (gm < NN){
        int d = (c - 2) * 2 + (k16 >> 5);
        int u = k16 & 31;
        int r = gm / WW, cc = gm - r * WW;
        int e = -1;
        if (d == 0){ if (r < HH-1) e = gm; }
        else if (d == 1){ if (cc >= 1) e = r*(WW-1) + cc - 1; }
        else if (d == 2){ if (r >= 1) e = gm - WW; }
        else            { if (cc <= WW-2) e = r*(WW-1) + cc; }
        if (e >= 0){
            const uint4* src = (const uint4*)(&g_EDGEH[d][0] + (size_t)e * 32 + u);
            hv[0] = src[0];
            hv[1] = src[1];
        }
    }
}

// ---------------- GEMM1: XQ(fp16) = relu(x @ Wcat), C=2 chunks ----------------
__global__ __launch_bounds__(512, 1) void k_tg1(const float* __restrict__ x){
    extern __shared__ char smem[];
    const uint32_t sb = smem_u32(smem);
    const int tid = threadIdx.x, wid = tid >> 5, lane = tid & 31;
    const int warp_m = wid >> 2, warp_n = wid & 3;
    const int M0 = blockIdx.x * 128;
    const int m = tid >> 2, k16 = (tid & 3) * 16, gm = M0 + m;

    float acc[2][4][4];
#pragma unroll
    for (int t = 0; t < 2; t++)
#pragma unroll
        for (int j = 0; j < 4; j++)
#pragma unroll
            for (int e = 0; e < 4; e++) acc[t][j][e] = 0.f;

    float4 v[4];
    cp_b(sb + SOF_B, (const char*)g_B1, tid);
    ldg_a_x(x, gm, 0, k16, v);

#pragma unroll
    for (int c = 0; c < 2; c++){
        uint32_t abase = (c & 1) ? SOF_A1 : SOF_A0;
        sts_a(smem, abase, v, m, k16);
        if (c == 0){
            cp_b(sb + SOF_B + 16384, (const char*)g_B1 + 16384, tid);
            ldg_a_x(x, gm, 1, k16, v);
            CP_WAIT1();
        } else {
            CP_WAIT0();
        }
        __syncthreads();
        mma_chunk64(sb + abase, sb + SOF_B + (c % 3) * 16384, warp_m, warp_n, lane, acc);
    }
#pragma unroll
    for (int tf = 0; tf < 2; tf++){
        int r0 = M0 + warp_m * 32 + tf * 16 + (lane >> 2);
#pragma unroll
        for (int j = 0; j < 4; j++){
            int col = warp_n * 32 + j * 8 + (lane & 3) * 2;
            if (r0 < NN)
                *(uint32_t*)(g_XQ + (size_t)r0 * 128 + col) =
                    pk_h2(fmaxf(acc[tf][j][0], 0.f), fmaxf(acc[tf][j][1], 0.f));
            if (r0 + 8 < NN)
                *(uint32_t*)(g_XQ + (size_t)(r0 + 8) * 128 + col) =
                    pk_h2(fmaxf(acc[tf][j][2], 0.f), fmaxf(acc[tf][j][3], 0.f));
        }
    }
}

// ---------------- GEMM2 + fused 2x2 pooling, C=4 chunks ----------------
__global__ __launch_bounds__(512, 1) void k_tg2(const float* __restrict__ x,
                                                float* __restrict__ out){
    extern __shared__ char smem[];
    const uint32_t sb = smem_u32(smem);
    const int tid = threadIdx.x, wid = tid >> 5, lane = tid & 31;
    const int warp_m = wid >> 2, warp_n = wid & 3;
    const int M0 = blockIdx.x * 128;
    const int m = tid >> 2, k16 = (tid & 3) * 16, gm = M0 + m;

    float acc[2][4][4];
#pragma unroll
    for (int t = 0; t < 2; t++)
#pragma unroll
        for (int j = 0; j < 4; j++)
#pragma unroll
            for (int e = 0; e < 4; e++) acc[t][j][e] = 0.f;

    float4 v[4];
    uint4 hv[2];
    cp_b(sb + SOF_B, (const char*)g_B2, tid);
    ldg_a_x(x, gm, 0, k16, v);

#pragma unroll
    for (int c = 0; c < 4; c++){
        uint32_t abase = (c & 1) ? SOF_A1 : SOF_A0;
        if (c < 2) sts_a(smem, abase, v, m, k16);
        else       sts_a16(smem, abase, hv, m, k16);
        if (c < 3){
            cp_b(sb + SOF_B + ((c + 1) % 3) * 16384,
                 (const char*)g_B2 + (size_t)(c + 1) * 16384, tid);
            if (c + 1 < 2) ldg_a_x(x, gm, c + 1, k16, v);
            else           ldg_a_agg16(gm, c + 1, k16, hv);
            CP_WAIT1();
        } else {
            CP_WAIT0();
        }
        __syncthreads();
        mma_chunk64(sb + abase, sb + SOF_B + (c % 3) * 16384, warp_m, warp_n, lane, acc);
    }

    // fused pooling epilogue: relu -> horizontal pair max via shuffle -> atomicMax
#pragma unroll
    for (int tf = 0; tf < 2; tf++){
#pragma unroll
        for (int half = 0; half < 2; half++){
            int r = M0 + warp_m * 32 + tf * 16 + (lane >> 2) + half * 8;
#pragma unroll
            for (int j = 0; j < 4; j++){
                float v0 = fmaxf(acc[tf][j][half*2 + 0], 0.f);
                float v1 = fmaxf(acc[tf][j][half*2 + 1], 0.f);
                float m0 = fmaxf(v0, __shfl_xor_sync(0xffffffffu, v0, 4));
                float m1 = fmaxf(v1, __shfl_xor_sync(0xffffffffu, v1, 4));
                if ((((lane >> 2) & 1) == 0) && r < NN){
                    int gr = r / WW, gc = r - gr * WW;
                    int p = (gr >> 1) * PCC + (gc >> 1);
                    int col = warp_n * 32 + j * 8 + (lane & 3) * 2;
                    atomicMax((int*)(out + (size_t)p * 128 + col),     __float_as_int(m0));
                    atomicMax((int*)(out + (size_t)p * 128 + col + 1), __float_as_int(m1));
                }
            }
        }
    }
}

// =====================================================================
// Edge GEMM (R9 structure): 128-edge tile, spread fill; fp16 output
// 256 threads, 8 warps; warp tile 16m x 32n; K=96 (6 kc)
// =====================================================================
__global__ __launch_bounds__(256, 4) void k_edge(const float* __restrict__ efN,
                                                 const float* __restrict__ efE,
                                                 const float* __restrict__ efS,
                                                 const float* __restrict__ efW,
                                                 int unused){
    extern __shared__ char smem[];
    const uint32_t sb = smem_u32(smem);
    const int q = blockIdx.y;
    const float* ef = (q==0) ? efN : (q==1) ? efE : (q==2) ? efS : efW;
    const int E = (q==0 || q==2) ? E_NS : E_EW;
    const int M0 = blockIdx.x * 128;
    if (M0 >= E) return;
    const int tid = threadIdx.x, wid = tid >> 5, lane = tid & 31;

    // fill A: 128 edges x 96 K (12 k8-chunks), spread across threads
#pragma unroll
    for (int i = 0; i < 6; i++){
        int lin = tid + 256 * i;
        int m = lin / 12, k8c = lin - m * 12;
        int k8 = k8c * 8;
        int e = M0 + m;
        uint4 H = make_uint4(0u, 0u, 0u, 0u);
        if (e < E){
            if (k8c < 4){
                const float* src = ef + (size_t)e * 32 + k8;
                float4 v0 = *(const float4*)(src);
                float4 v1 = *(const float4*)(src + 4);
                H.x = pk_h2(v0.x, v0.y); H.y = pk_h2(v0.z, v0.w);
                H.z = pk_h2(v1.x, v1.y); H.w = pk_h2(v1.z, v1.w);
            } else {
                int s, t;
                if (q == 0){ s = e + WW; t = e; }
                else if (q == 2){ s = e; t = e + WW; }
                else { int r = e / (WW - 1); if (q == 1){ s = e + r; t = s + 1; } else { t = e + r; s = t + 1; } }
                int node = (k8c < 8) ? s : t;
                int u = (k8c & 3) * 8;
                H = *(const uint4*)(g_XQ + (size_t)node * 128 + q * 32 + u);
            }
        }
        *(uint4*)(smem + EOF_A + swoff256(m, k8)) = H;
    }
    {
        const uint4* bh = (const uint4*)g_BE[q];
#pragma unroll
        for (int i = 0; i < 2; i++){
            int idx = tid + 256 * i;
            ((uint4*)(smem + EOF_B))[idx] = bh[idx];
        }
    }
    __syncthreads();

    float acc[4][4];
#pragma unroll
    for (int j = 0; j < 4; j++)
#pragma unroll
        for (int e = 0; e < 4; e++) acc[j][e] = 0.f;

#pragma unroll
    for (int kc = 0; kc < 6; kc++){
        uint32_t a[4];
        {
            int row = wid * 16 + (lane & 15);
            int ch = kc * 2 + (lane >> 4);
            uint32_t off = row * 256 + ((ch ^ (row & 7)) << 4);
            LDSM_X4(a[0], a[1], a[2], a[3], sb + EOF_A + off);
        }
        uint32_t bfr[4][2];
#pragma unroll
        for (int jj = 0; jj < 2; jj++){
            int rowN = jj * 16 + (lane & 7) + ((lane >> 4) << 3);
            int ch = kc * 2 + ((lane >> 3) & 1);
            uint32_t off = rowN * 256 + ((ch ^ (rowN & 7)) << 4);
            uint32_t r0, r1, r2, r3;
            LDSM_X4(r0, r1, r2, r3, sb + EOF_B + off);
            bfr[jj*2][0] = r0;   bfr[jj*2][1] = r1;
            bfr[jj*2+1][0] = r2; bfr[jj*2+1][1] = r3;
        }
#pragma unroll
        for (int j = 0; j < 4; j++)
            mma_f16(acc[j], a, bfr[j][0], bfr[j][1]);
    }

    __half* ED = &g_EDGEH[q][0];
    int r0 = M0 + wid * 16 + (lane >> 2);
#pragma unroll
    for (int j = 0; j < 4; j++){
        int col = j * 8 + (lane & 3) * 2;
        if (r0 < E)
            *(uint32_t*)(ED + (size_t)r0 * 32 + col) =
                pk_h2(fmaxf(acc[j][0], 0.f), fmaxf(acc[j][1], 0.f));
        if (r0 + 8 < E)
            *(uint32_t*)(ED + (size_t)(r0 + 8) * 32 + col) =
                pk_h2(fmaxf(acc[j][2], 0.f), fmaxf(acc[j][3], 0.f));
    }
}

// ---------------- metadata / edge-feature kernels ----------------
__global__ void k_meta(float* __restrict__ out){
    int t = blockIdx.x * 256 + threadIdx.x;
    if (t < NP){
        out[OFF_POS + 2*t]     = (float)(t / PCC);
        out[OFF_POS + 2*t + 1] = (float)(t % PCC);
        return;
    }
    t -= NP;
    if (t < M_NS){
        int k = 1 + t / PCC, j = t % PCC;
        out[OFF_EIN + 2*t]     = (float)(k*PCC + j);
        out[OFF_EIN + 2*t + 1] = (float)((k-1)*PCC + j);
        return;
    }
    t -= M_NS;
    if (t < M_EW){
        int k = t / 217, j = t % 217;
        int s = k*PCC + j;
        out[OFF_EIE + 2*t]     = (float)s;
        out[OFF_EIE + 2*t + 1] = (float)(s + 1);
        return;
    }
    t -= M_EW;
    if (t < M_NS){
        int k = t / PCC, j = t % PCC;
        int s = k*PCC + j;
        out[OFF_EIS + 2*t]     = (float)s;
        out[OFF_EIS + 2*t + 1] = (float)(s + PCC);
        return;
    }
    t -= M_NS;
    if (t < M_EW){
        int k = t / 217, j = t % 217 + 1;
        int s = k*PCC + j;
        out[OFF_EIW + 2*t]     = (float)s;
        out[OFF_EIW + 2*t + 1] = (float)(s - 1);
        return;
    }
}

__global__ void k_efeat(float* __restrict__ out){
    const int d = blockIdx.y;
    const int M = (d == 0 || d == 2) ? M_NS : M_EW;
    int t = blockIdx.x * 256 + threadIdx.x;
    if (t >= M * 4) return;
    int m = t >> 2, fi = (t & 3) * 8;   // 8 halves = 16B per thread
    int e1, stride2 = 1; bool two = true; size_t off;
    if (d == 0){      int k = 1 + m/PCC, j = m%PCC; e1 = (2*k - 1)*WW + 2*j;      off = OFF_FN; }
    else if (d == 1){ int k = m/217,     j = m%217; e1 = 2*k*(WW-1) + 2*j + 1;    stride2 = WW-1; two = (k < 247); off = OFF_FE; }
    else if (d == 2){ int k = m/PCC,     j = m%PCC; e1 = (2*k + 1)*WW + 2*j;      off = OFF_FS; }
    else {            int k = m/217,     j = m%217 + 1; e1 = 2*k*(WW-1) + 2*j - 1; stride2 = WW-1; two = (k < 247); off = OFF_FW; }
    const __half* ED = &g_EDGEH[d][0];
    uint4 A = *(const uint4*)(ED + (size_t)e1*32 + fi);
    uint4 B = two ? *(const uint4*)(ED + (size_t)(e1 + stride2)*32 + fi) : make_uint4(0u,0u,0u,0u);
    float* o = out + off + (size_t)m*32 + fi;
    const uint32_t* aw = &A.x;
    const uint32_t* bw = &B.x;
#pragma unroll
    for (int w = 0; w < 4; w++){
        float2 fa = __half22float2(*(const __half2*)&aw[w]);
        float2 fb = __half22float2(*(const __half2*)&bw[w]);
        o[2*w]   = fmaxf(fa.x, fb.x);
        o[2*w+1] = fmaxf(fa.y, fb.y);
    }
}

// =====================================================================
extern "C" void kernel_launch(void* const* d_in, const int* in_sizes, int n_in,
                              void* d_out, int out_size){
    const float* x     = (const float*)d_in[0];
    const float* efN   = (const float*)d_in[6];
    const float* efE   = (const float*)d_in[7];
    const float* efS   = (const float*)d_in[8];
    const float* efW   = (const float*)d_in[9];
    const float* Wemb  = (const float*)d_in[10];
    const float* Wedge = (const float*)d_in[11];
    const float* Wnode = (const float*)d_in[12];
    float* out = (float*)d_out;

    static bool attr_done = false;
    if (!attr_done){
        cudaFuncSetAttribute(k_tg1, cudaFuncAttributeMaxDynamicSharedMemorySize, SMEM_TG);
        cudaFuncSetAttribute(k_tg2, cudaFuncAttributeMaxDynamicSharedMemorySize, SMEM_TG);
        cudaFuncSetAttribute(k_edge, cudaFuncAttributeMaxDynamicSharedMemorySize, SMEM_TE);
        attr_done = true;
    }

    const int gm = (NN + 127) / 128;             // 1687 tiles
    k_conv_w<<<(65536 + 255)/256, 256>>>(Wemb, Wnode, Wedge);
    k_init<<<(NP*32 + 255)/256, 256>>>(out);
    k_tg1<<<gm, 512, SMEM_TG>>>(x);
    dim3 ge((E_NS + 127) / 128, 4);
    k_edge<<<ge, 256, SMEM_TE>>>(efN, efE, efS, efW, 0);
    k_tg2<<<gm, 512, SMEM_TG>>>(x, out);

    const int metaT = NP + 2*M_NS + 2*M_EW;
    dim3 gf((M_NS*4 + 255) / 256, 4);
    k_meta<<<(metaT + 255)/256, 256>>>(out);
    k_efeat<<<gf, 256>>>(out);
}

// round 14
// speedup vs baseline: 1.0743x; 1.0392x over previous
#include <cuda_runtime.h>
#include <cuda_fp16.h>
#include <cstdint>

// ---------------- static problem constants ----------------
#define HH 495
#define WW 436
#define NN (HH*WW)            // 215820 nodes
#define PRR 248
#define PCC 218
#define NP (PRR*PCC)          // 54064 pooled nodes
#define E_NS ((HH-1)*WW)      // 215384 edges (north & south)
#define E_EW (HH*(WW-1))      // 215325 edges (east & west)
#define M_NS (247*218)
#define M_EW (248*217)

// output layout (float elements)
#define OFF_POS 6920192
#define OFF_EIN 7028320
#define OFF_EIE 7136012
#define OFF_EIS 7243644
#define OFF_EIW 7351336
#define OFF_FN  7458968
#define OFF_FE  9182040
#define OFF_FS  10904152
#define OFF_FW  12627224
#define OUT_TOTAL 14349336

// ---------------- scratch ----------------
__device__ __align__(16) __half g_XQ[(size_t)NN*128];        // fp16
__device__ __align__(16) __half g_EDGEH[4][(size_t)E_NS*32]; // fp16 edge MLP outputs
__device__ __align__(16) __half g_B1[2][128*64];
__device__ __align__(16) __half g_B2[4][128*64];
__device__ __align__(16) __half g_BE[4][32*128];

// ---------------- helpers ----------------
__device__ __forceinline__ uint32_t smem_u32(const void* p){
    uint32_t a;
    asm("{ .reg .u64 t; cvta.to.shared.u64 t, %1; cvt.u32.u64 %0, t; }" : "=r"(a) : "l"(p));
    return a;
}
__device__ __forceinline__ uint32_t swoff64(int row, int k){
    return (uint32_t)(row * 128 + (((k >> 3) ^ (row & 7)) << 4) + (k & 7) * 2);
}
__device__ __forceinline__ uint32_t swoff256(int row, int k){
    return (uint32_t)(row * 256 + (((k >> 3) ^ (row & 7)) << 4) + (k & 7) * 2);
}
__device__ __forceinline__ uint32_t pk_h2(float a, float b){
    __half2 h = __floats2half2_rn(a, b);
    return *reinterpret_cast<uint32_t*>(&h);
}

#define LDSM_X4(r0,r1,r2,r3,addr) \
    asm volatile("ldmatrix.sync.aligned.m8n8.x4.shared.b16 {%0,%1,%2,%3}, [%4];" \
        : "=r"(r0), "=r"(r1), "=r"(r2), "=r"(r3) : "r"(addr))

__device__ __forceinline__ void mma_f16(float* c, const uint32_t* a, uint32_t b0, uint32_t b1){
    asm volatile(
        "mma.sync.aligned.m16n8k16.row.col.f32.f16.f16.f32 "
        "{%0,%1,%2,%3}, {%4,%5,%6,%7}, {%8,%9}, {%0,%1,%2,%3};"
        : "+f"(c[0]), "+f"(c[1]), "+f"(c[2]), "+f"(c[3])
        : "r"(a[0]), "r"(a[1]), "r"(a[2]), "r"(a[3]), "r"(b0), "r"(b1));
}

#define CP16(dst, src) asm volatile("cp.async.cg.shared.global [%0], [%1], 16;" :: "r"(dst), "l"(src))
#define CP_COMMIT()    asm volatile("cp.async.commit_group;" ::: "memory")
#define CP_WAIT0()     asm volatile("cp.async.wait_group 0;" ::: "memory")
#define CP_WAIT1()     asm volatile("cp.async.wait_group 1;" ::: "memory")

// smem layout node GEMMs: A double buffer + B triple ring (staging reuses [0,34816))
#define SOF_A0 0
#define SOF_A1 16384
#define SOF_B  32768
#define SMEM_TG 81920
// edge GEMM: A tile + B + staging (80B-stride rows)
#define EOF_A 0
#define EOF_B 32768
#define EOF_S 40960             // 128 rows x 80B = 10240
#define SMEM_TE 51200

// ---------------- weight preconversion ----------------
__global__ void k_conv_w(const float* __restrict__ Wemb, const float* __restrict__ Wnode,
                         const float* __restrict__ Wedge){
    int t = blockIdx.x * 256 + threadIdx.x;
    if (t < 16384){
        int n = t >> 7, kg = t & 127;
        int c = kg >> 6, k = kg & 63;
        float w = Wemb[(n >> 5) * 4096 + kg * 32 + (n & 31)];
        *(__half*)((char*)g_B1 + (uint32_t)c * 16384 + swoff64(n, k)) = __float2half_rn(w);
        return;
    }
    t -= 16384;
    if (t < 32768){
        int n = t >> 8, kg = t & 255;
        int c = kg >> 6, k = kg & 63;
        float w = Wnode[kg * 128 + n];
        if (kg >= 128) w *= 0.25f;
        *(__half*)((char*)g_B2 + (uint32_t)c * 16384 + swoff64(n, k)) = __float2half_rn(w);
        return;
    }
    t -= 32768;
    if (t < 16384){
        int q = t >> 12, r = t & 4095;
        int n = r >> 7, k = r & 127;
        float w = (k < 96) ? Wedge[q * 3072 + k * 32 + n] : 0.f;
        *(__half*)((char*)g_BE[q] + swoff256(n, k)) = __float2half_rn(w);
    }
}

// ---------------- single-pass fp16 MMA over one 64-K chunk (warp tile 32x32) ----------------
__device__ __forceinline__ void mma_chunk64(uint32_t Ab, uint32_t Bb,
                                            int warp_m, int warp_n, int lane, float acc[2][4][4]){
#pragma unroll
    for (int kc = 0; kc < 4; kc++){
        uint32_t a[2][4];
#pragma unroll
        for (int tf = 0; tf < 2; tf++){
            int row = warp_m * 32 + tf * 16 + (lane & 15);
            int ch = kc * 2 + (lane >> 4);
            uint32_t off = row * 128 + ((ch ^ (row & 7)) << 4);
            LDSM_X4(a[tf][0], a[tf][1], a[tf][2], a[tf][3], Ab + off);
        }
        uint32_t bfr[4][2];
#pragma unroll
        for (int jj = 0; jj < 2; jj++){
            int rowN = warp_n * 32 + jj * 16 + (lane & 7) + ((lane >> 4) << 3);
            int ch = kc * 2 + ((lane >> 3) & 1);
            uint32_t off = rowN * 128 + ((ch ^ (rowN & 7)) << 4);
            uint32_t r0, r1, r2, r3;
            LDSM_X4(r0, r1, r2, r3, Bb + off);
            bfr[jj*2][0] = r0;   bfr[jj*2][1] = r1;
            bfr[jj*2+1][0] = r2; bfr[jj*2+1][1] = r3;
        }
#pragma unroll
        for (int tf = 0; tf < 2; tf++)
#pragma unroll
            for (int j = 0; j < 4; j++)
                mma_f16(acc[tf][j], a[tf], bfr[j][0], bfr[j][1]);
    }
}

// fp32 regs -> fp16 swizzled smem A buffer
__device__ __forceinline__ void sts_a(char* smem, uint32_t abase, const float4 v[4], int m, int k16){
    uint4 H0, H1;
    H0.x = pk_h2(v[0].x, v[0].y); H0.y = pk_h2(v[0].z, v[0].w);
    H0.z = pk_h2(v[1].x, v[1].y); H0.w = pk_h2(v[1].z, v[1].w);
    H1.x = pk_h2(v[2].x, v[2].y); H1.y = pk_h2(v[2].z, v[2].w);
    H1.z = pk_h2(v[3].x, v[3].y); H1.w = pk_h2(v[3].z, v[3].w);
    *(uint4*)(smem + abase + swoff64(m, k16))     = H0;
    *(uint4*)(smem + abase + swoff64(m, k16 + 8)) = H1;
}
__device__ __forceinline__ void sts_a16(char* smem, uint32_t abase, const uint4 hv[2], int m, int k16){
    *(uint4*)(smem + abase + swoff64(m, k16))     = hv[0];
    *(uint4*)(smem + abase + swoff64(m, k16 + 8)) = hv[1];
}

__device__ __forceinline__ void cp_b(uint32_t sbuf, const char* src, int tid){
#pragma unroll
    for (int i = 0; i < 2; i++){
        uint32_t o = (uint32_t)(tid + 512 * i) * 16;
        CP16(sbuf + o, src + o);
    }
    CP_COMMIT();
}

// A-chunk loaders (thread: node row gm, 16 values at k16); gm<0 => zero
__device__ __forceinline__ void ldg_a_x(const float* __restrict__ x, int gm, int c, int k16, float4 v[4]){
    v[0] = v[1] = v[2] = v[3] = make_float4(0.f,0.f,0.f,0.f);
    if (gm >= 0){
        const float* src = x + (size_t)gm * 128 + c * 64 + k16;
        v[0] = *(const float4*)(src);
        v[1] = *(const float4*)(src + 4);
        v[2] = *(const float4*)(src + 8);
        v[3] = *(const float4*)(src + 12);
    }
}
__device__ __forceinline__ void ldg_a_agg16(int gm, int c, int k16, uint4 hv[2]){
    hv[0] = make_uint4(0u,0u,0u,0u); hv[1] = hv[0];
    if (gm >= 0){
        int d = (c - 2) * 2 + (k16 >> 5);
        int u = k16 & 31;
        int r = gm / WW, cc = gm - r * WW;
        int e = -1;
        if (d == 0){ if (r < HH-1) e = gm; }
        else if (d == 1){ if (cc >= 1) e = r*(WW-1) + cc - 1; }
        else if (d == 2){ if (r >= 1) e = gm - WW; }
        else            { if (cc <= WW-2) e = r*(WW-1) + cc; }
        if (e >= 0){
            const uint4* src = (const uint4*)(&g_EDGEH[d][0] + (size_t)e * 32 + u);
            hv[0] = src[0];
            hv[1] = src[1];
        }
    }
}

// ---------------- GEMM1: XQ(fp16) = relu(x @ Wcat), C=2, smem-staged epilogue ----------------
__global__ __launch_bounds__(512, 1) void k_tg1(const float* __restrict__ x){
    extern __shared__ char smem[];
    const uint32_t sb = smem_u32(smem);
    const int tid = threadIdx.x, wid = tid >> 5, lane = tid & 31;
    const int warp_m = wid >> 2, warp_n = wid & 3;
    const int M0 = blockIdx.x * 128;
    const int m = tid >> 2, k16 = (tid & 3) * 16;
    const int gm0 = (M0 + m < NN) ? (M0 + m) : -1;

    float acc[2][4][4];
#pragma unroll
    for (int t = 0; t < 2; t++)
#pragma unroll
        for (int j = 0; j < 4; j++)
#pragma unroll
            for (int e = 0; e < 4; e++) acc[t][j][e] = 0.f;

    float4 v[4];
    cp_b(sb + SOF_B, (const char*)g_B1, tid);
    ldg_a_x(x, gm0, 0, k16, v);

#pragma unroll
    for (int c = 0; c < 2; c++){
        uint32_t abase = (c & 1) ? SOF_A1 : SOF_A0;
        sts_a(smem, abase, v, m, k16);
        if (c == 0){
            cp_b(sb + SOF_B + 16384, (const char*)g_B1 + 16384, tid);
            ldg_a_x(x, gm0, 1, k16, v);
            CP_WAIT1();
        } else {
            CP_WAIT0();
        }
        __syncthreads();
        mma_chunk64(sb + abase, sb + SOF_B + (c % 3) * 16384, warp_m, warp_n, lane, acc);
    }
    // staged epilogue: fragments -> smem (272B rows, conflict-free) -> coalesced uint4 STG
    __syncthreads();
#pragma unroll
    for (int tf = 0; tf < 2; tf++){
        int r0 = warp_m * 32 + tf * 16 + (lane >> 2);
#pragma unroll
        for (int j = 0; j < 4; j++){
            int col = warp_n * 32 + j * 8 + (lane & 3) * 2;
            *(uint32_t*)(smem + r0 * 272 + col * 2) =
                pk_h2(fmaxf(acc[tf][j][0], 0.f), fmaxf(acc[tf][j][1], 0.f));
            *(uint32_t*)(smem + (r0 + 8) * 272 + col * 2) =
                pk_h2(fmaxf(acc[tf][j][2], 0.f), fmaxf(acc[tf][j][3], 0.f));
        }
    }
    __syncthreads();
#pragma unroll
    for (int i = 0; i < 4; i++){
        int idx = tid + 512 * i;          // 0..2047
        int r = idx >> 4, c16 = idx & 15;
        if (M0 + r < NN)
            *(uint4*)(g_XQ + (size_t)(M0 + r) * 128 + c16 * 8) =
                *(const uint4*)(smem + r * 272 + c16 * 16);
    }
}

// ---------------- GEMM2 + fused pooling via pooled-cell tiles, direct writes ----------------
__global__ __launch_bounds__(512, 1) void k_tg2(const float* __restrict__ x,
                                                float* __restrict__ out){
    extern __shared__ char smem[];
    const uint32_t sb = smem_u32(smem);
    const int tid = threadIdx.x, wid = tid >> 5, lane = tid & 31;
    const int warp_m = wid >> 2, warp_n = wid & 3;
    const int P0 = blockIdx.x * 32;      // 32 pooled cells per tile
    const int m = tid >> 2, k16 = (tid & 3) * 16;
    // row m -> node gm via pooled-cell permutation
    int gm0;
    {
        int cell = P0 + (m >> 2);
        int j = m & 3;
        gm0 = -1;
        if (cell < NP){
            int pr = cell / PCC, pc = cell - pr * PCC;
            int gr = 2 * pr + (j >> 1), gc = 2 * pc + (j & 1);
            if (gr < HH) gm0 = gr * WW + gc;
        }
    }

    float acc[2][4][4];
#pragma unroll
    for (int t = 0; t < 2; t++)
#pragma unroll
        for (int j = 0; j < 4; j++)
#pragma unroll
            for (int e = 0; e < 4; e++) acc[t][j][e] = 0.f;

    float4 v[4];
    uint4 hv[2];
    cp_b(sb + SOF_B, (const char*)g_B2, tid);
    ldg_a_x(x, gm0, 0, k16, v);

#pragma unroll
    for (int c = 0; c < 4; c++){
        uint32_t abase = (c & 1) ? SOF_A1 : SOF_A0;
        if (c < 2) sts_a(smem, abase, v, m, k16);
        else       sts_a16(smem, abase, hv, m, k16);
        if (c < 3){
            cp_b(sb + SOF_B + ((c + 1) % 3) * 16384,
                 (const char*)g_B2 + (size_t)(c + 1) * 16384, tid);
            if (c + 1 < 2) ldg_a_x(x, gm0, c + 1, k16, v);
            else           ldg_a_agg16(gm0, c + 1, k16, hv);
            CP_WAIT1();
        } else {
            CP_WAIT0();
        }
        __syncthreads();
        mma_chunk64(sb + abase, sb + SOF_B + (c % 3) * 16384, warp_m, warp_n, lane, acc);
    }

    // pooling epilogue: rows 4i..4i+3 = one pooled cell -> butterfly max -> direct store
#pragma unroll
    for (int tf = 0; tf < 2; tf++){
#pragma unroll
        for (int half = 0; half < 2; half++){
            int mloc = warp_m * 32 + tf * 16 + half * 8 + (lane >> 2);
#pragma unroll
            for (int jf = 0; jf < 4; jf++){
                float v0 = fmaxf(acc[tf][jf][half*2 + 0], 0.f);
                float v1 = fmaxf(acc[tf][jf][half*2 + 1], 0.f);
                v0 = fmaxf(v0, __shfl_xor_sync(0xffffffffu, v0, 4));
                v0 = fmaxf(v0, __shfl_xor_sync(0xffffffffu, v0, 8));
                v1 = fmaxf(v1, __shfl_xor_sync(0xffffffffu, v1, 4));
                v1 = fmaxf(v1, __shfl_xor_sync(0xffffffffu, v1, 8));
                if (((lane >> 2) & 3) == 0){
                    int p = P0 + (mloc >> 2);
                    if (p < NP){
                        int col = warp_n * 32 + jf * 8 + (lane & 3) * 2;
                        *(float2*)(out + (size_t)p * 128 + col) = make_float2(v0, v1);
                    }
                }
            }
        }
    }
}

// =====================================================================
// Edge GEMM: 128-edge tile, spread fill; smem-staged coalesced fp16 output
// =====================================================================
__global__ __launch_bounds__(256, 4) void k_edge(const float* __restrict__ efN,
                                                 const float* __restrict__ efE,
                                                 const float* __restrict__ efS,
                                                 const float* __restrict__ efW,
                                                 int unused){
    extern __shared__ char smem[];
    const uint32_t sb = smem_u32(smem);
    const int q = blockIdx.y;
    const float* ef = (q==0) ? efN : (q==1) ? efE : (q==2) ? efS : efW;
    const int E = (q==0 || q==2) ? E_NS : E_EW;
    const int M0 = blockIdx.x * 128;
    if (M0 >= E) return;
    const int tid = threadIdx.x, wid = tid >> 5, lane = tid & 31;

#pragma unroll
    for (int i = 0; i < 6; i++){
        int lin = tid + 256 * i;
        int m = lin / 12, k8c = lin - m * 12;
        int k8 = k8c * 8;
        int e = M0 + m;
        uint4 H = make_uint4(0u, 0u, 0u, 0u);
        if (e < E){
            if (k8c < 4){
                const float* src = ef + (size_t)e * 32 + k8;
                float4 v0 = *(const float4*)(src);
                float4 v1 = *(const float4*)(src + 4);
                H.x = pk_h2(v0.x, v0.y); H.y = pk_h2(v0.z, v0.w);
                H.z = pk_h2(v1.x, v1.y); H.w = pk_h2(v1.z, v1.w);
            } else {
                int s, t;
                if (q == 0){ s = e + WW; t = e; }
                else if (q == 2){ s = e; t = e + WW; }
                else { int r = e / (WW - 1); if (q == 1){ s = e + r; t = s + 1; } else { t = e + r; s = t + 1; } }
                int node = (k8c < 8) ? s : t;
                int u = (k8c & 3) * 8;
                H = *(const uint4*)(g_XQ + (size_t)node * 128 + q * 32 + u);
            }
        }
        *(uint4*)(smem + EOF_A + swoff256(m, k8)) = H;
    }
    {
        const uint4* bh = (const uint4*)g_BE[q];
#pragma unroll
        for (int i = 0; i < 2; i++){
            int idx = tid + 256 * i;
            ((uint4*)(smem + EOF_B))[idx] = bh[idx];
        }
    }
    __syncthreads();

    float acc[4][4];
#pragma unroll
    for (int j = 0; j < 4; j++)
#pragma unroll
        for (int e = 0; e < 4; e++) acc[j][e] = 0.f;

#pragma unroll
    for (int kc = 0; kc < 6; kc++){
        uint32_t a[4];
        {
            int row = wid * 16 + (lane & 15);
            int ch = kc * 2 + (lane >> 4);
            uint32_t off = row * 256 + ((ch ^ (row & 7)) << 4);
            LDSM_X4(a[0], a[1], a[2], a[3], sb + EOF_A + off);
        }
        uint32_t bfr[4][2];
#pragma unroll
        for (int jj = 0; jj < 2; jj++){
            int rowN = jj * 16 + (lane & 7) + ((lane >> 4) << 3);
            int ch = kc * 2 + ((lane >> 3) & 1);
            uint32_t off = rowN * 256 + ((ch ^ (rowN & 7)) << 4);
            uint32_t r0, r1, r2, r3;
            LDSM_X4(r0, r1, r2, r3, sb + EOF_B + off);
            bfr[jj*2][0] = r0;   bfr[jj*2][1] = r1;
            bfr[jj*2+1][0] = r2; bfr[jj*2+1][1] = r3;
        }
#pragma unroll
        for (int j = 0; j < 4; j++)
            mma_f16(acc[j], a, bfr[j][0], bfr[j][1]);
    }

    // staged epilogue: fragments -> smem (80B rows) -> coalesced 64B-row STG
    __syncthreads();
    {
        int r0 = wid * 16 + (lane >> 2);
#pragma unroll
        for (int j = 0; j < 4; j++){
            int col = j * 8 + (lane & 3) * 2;
            *(uint32_t*)(smem + EOF_S + r0 * 80 + col * 2) =
                pk_h2(fmaxf(acc[j][0], 0.f), fmaxf(acc[j][1], 0.f));
            *(uint32_t*)(smem + EOF_S + (r0 + 8) * 80 + col * 2) =
                pk_h2(fmaxf(acc[j][2], 0.f), fmaxf(acc[j][3], 0.f));
        }
    }
    __syncthreads();
    {
        __half* ED = &g_EDGEH[q][0];
#pragma unroll
        for (int i = 0; i < 2; i++){
            int idx = tid + 256 * i;          // 0..511
            int r = idx >> 2, c = idx & 3;
            int e = M0 + r;
            if (e < E)
                *(uint4*)(ED + (size_t)e * 32 + c * 8) =
                    *(const uint4*)(smem + EOF_S + r * 80 + c * 16);
        }
    }
}

// ---------------- metadata / edge-feature kernels ----------------
__global__ void k_meta(float* __restrict__ out){
    int t = blockIdx.x * 256 + threadIdx.x;
    if (t < NP){
        out[OFF_POS + 2*t]     = (float)(t / PCC);
        out[OFF_POS + 2*t + 1] = (float)(t % PCC);
        return;
    }
    t -= NP;
    if (t < M_NS){
        int k = 1 + t / PCC, j = t % PCC;
        out[OFF_EIN + 2*t]     = (float)(k*PCC + j);
        out[OFF_EIN + 2*t + 1] = (float)((k-1)*PCC + j);
        return;
    }
    t -= M_NS;
    if (t < M_EW){
        int k = t / 217, j = t % 217;
        int s = k*PCC + j;
        out[OFF_EIE + 2*t]     = (float)s;
        out[OFF_EIE + 2*t + 1] = (float)(s + 1);
        return;
    }
    t -= M_EW;
    if (t < M_NS){
        int k = t / PCC, j = t % PCC;
        int s = k*PCC + j;
        out[OFF_EIS + 2*t]     = (float)s;
        out[OFF_EIS + 2*t + 1] = (float)(s + PCC);
        return;
    }
    t -= M_NS;
    if (t < M_EW){
        int k = t / 217, j = t % 217 + 1;
        int s = k*PCC + j;
        out[OFF_EIW + 2*t]     = (float)s;
        out[OFF_EIW + 2*t + 1] = (float)(s - 1);
        return;
    }
}

__global__ void k_efeat(float* __restrict__ out){
    const int d = blockIdx.y;
    const int M = (d == 0 || d == 2) ? M_NS : M_EW;
    int t = blockIdx.x * 256 + threadIdx.x;
    if (t >= M * 4) return;
    int m = t >> 2, fi = (t & 3) * 8;
    int e1, stride2 = 1; bool two = true; size_t off;
    if (d == 0){      int k = 1 + m/PCC, j = m%PCC; e1 = (2*k - 1)*WW + 2*j;      off = OFF_FN; }
    else if (d == 1){ int k = m/217,     j = m%217; e1 = 2*k*(WW-1) + 2*j + 1;    stride2 = WW-1; two = (k < 247); off = OFF_FE; }
    else if (d == 2){ int k = m/PCC,     j = m%PCC; e1 = (2*k + 1)*WW + 2*j;      off = OFF_FS; }
    else {            int k = m/217,     j = m%217 + 1; e1 = 2*k*(WW-1) + 2*j - 1; stride2 = WW-1; two = (k < 247); off = OFF_FW; }
    const __half* ED = &g_EDGEH[d][0];
    uint4 A = *(const uint4*)(ED + (size_t)e1*32 + fi);
    uint4 B = two ? *(const uint4*)(ED + (size_t)(e1 + stride2)*32 + fi) : make_uint4(0u,0u,0u,0u);
    float* o = out + off + (size_t)m*32 + fi;
    const uint32_t* aw = &A.x;
    const uint32_t* bw = &B.x;
#pragma unroll
    for (int w = 0; w < 4; w++){
        float2 fa = __half22float2(*(const __half2*)&aw[w]);
        float2 fb = __half22float2(*(const __half2*)&bw[w]);
        o[2*w]   = fmaxf(fa.x, fb.x);
        o[2*w+1] = fmaxf(fa.y, fb.y);
    }
}

// =====================================================================
extern "C" void kernel_launch(void* const* d_in, const int* in_sizes, int n_in,
                              void* d_out, int out_size){
    const float* x     = (const float*)d_in[0];
    const float* efN   = (const float*)d_in[6];
    const float* efE   = (const float*)d_in[7];
    const float* efS   = (const float*)d_in[8];
    const float* efW   = (const float*)d_in[9];
    const float* Wemb  = (const float*)d_in[10];
    const float* Wedge = (const float*)d_in[11];
    const float* Wnode = (const float*)d_in[12];
    float* out = (float*)d_out;

    static bool attr_done = false;
    if (!attr_done){
        cudaFuncSetAttribute(k_tg1, cudaFuncAttributeMaxDynamicSharedMemorySize, SMEM_TG);
        cudaFuncSetAttribute(k_tg2, cudaFuncAttributeMaxDynamicSharedMemorySize, SMEM_TG);
        cudaFuncSetAttribute(k_edge, cudaFuncAttributeMaxDynamicSharedMemorySize, SMEM_TE);
        attr_done = true;
    }

    const int gm = (NN + 127) / 128;             // 1687 tiles
    const int gp = (NP + 31) / 32;               // 1690 pooled tiles
    k_conv_w<<<(65536 + 255)/256, 256>>>(Wemb, Wnode, Wedge);
    k_tg1<<<gm, 512, SMEM_TG>>>(x);
    dim3 ge((E_NS + 127) / 128, 4);
    k_edge<<<ge, 256, SMEM_TE>>>(efN, efE, efS, efW, 0);
    k_tg2<<<gp, 512, SMEM_TG>>>(x, out);

    const int metaT = NP + 2*M_NS + 2*M_EW;
    dim3 gf((M_NS*4 + 255) / 256, 4);
    k_meta<<<(metaT + 255)/256, 256>>>(out);
    k_efeat<<<gf, 256>>>(out);
}

// round 17
// speedup vs baseline: 1.1389x; 1.0601x over previous
#include <cuda_runtime.h>
#include <cuda_fp16.h>
#include <cstdint>

// ---------------- static problem constants ----------------
#define HH 495
#define WW 436
#define NN (HH*WW)            // 215820 nodes
#define PRR 248
#define PCC 218
#define NP (PRR*PCC)          // 54064 pooled nodes
#define E_NS ((HH-1)*WW)      // 215384 edges (north & south)
#define E_EW (HH*(WW-1))      // 215325 edges (east & west)
#define M_NS (247*218)
#define M_EW (248*217)

// output layout (float elements)
#define OFF_POS 6920192
#define OFF_EIN 7028320
#define OFF_EIE 7136012
#define OFF_EIS 7243644
#define OFF_EIW 7351336
#define OFF_FN  7458968
#define OFF_FE  9182040
#define OFF_FS  10904152
#define OFF_FW  12627224
#define OUT_TOTAL 14349336

// ---------------- scratch ----------------
__device__ __align__(16) __half g_XQ[(size_t)NN*128];        // fp16
__device__ __align__(16) __half g_EDGEH[4][(size_t)E_NS*32]; // fp16 edge MLP outputs
__device__ __align__(16) __half g_B1[2][128*64];
__device__ __align__(16) __half g_B2[4][128*64];
__device__ __align__(16) __half g_BE[4][32*128];

// ---------------- helpers ----------------
__device__ __forceinline__ uint32_t smem_u32(const void* p){
    uint32_t a;
    asm("{ .reg .u64 t; cvta.to.shared.u64 t, %1; cvt.u32.u64 %0, t; }" : "=r"(a) : "l"(p));
    return a;
}
__device__ __forceinline__ uint32_t swoff64(int row, int k){
    return (uint32_t)(row * 128 + (((k >> 3) ^ (row & 7)) << 4) + (k & 7) * 2);
}
__device__ __forceinline__ uint32_t swoff256(int row, int k){
    return (uint32_t)(row * 256 + (((k >> 3) ^ (row & 7)) << 4) + (k & 7) * 2);
}
__device__ __forceinline__ uint32_t pk_h2(float a, float b){
    __half2 h = __floats2half2_rn(a, b);
    return *reinterpret_cast<uint32_t*>(&h);
}

#define LDSM_X4(r0,r1,r2,r3,addr) \
    asm volatile("ldmatrix.sync.aligned.m8n8.x4.shared.b16 {%0,%1,%2,%3}, [%4];" \
        : "=r"(r0), "=r"(r1), "=r"(r2), "=r"(r3) : "r"(addr))

__device__ __forceinline__ void mma_f16(float* c, const uint32_t* a, uint32_t b0, uint32_t b1){
    asm volatile(
        "mma.sync.aligned.m16n8k16.row.col.f32.f16.f16.f32 "
        "{%0,%1,%2,%3}, {%4,%5,%6,%7}, {%8,%9}, {%0,%1,%2,%3};"
        : "+f"(c[0]), "+f"(c[1]), "+f"(c[2]), "+f"(c[3])
        : "r"(a[0]), "r"(a[1]), "r"(a[2]), "r"(a[3]), "r"(b0), "r"(b1));
}

#define CP16(dst, src) asm volatile("cp.async.cg.shared.global [%0], [%1], 16;" :: "r"(dst), "l"(src))
#define CP_COMMIT()    asm volatile("cp.async.commit_group;" ::: "memory")
#define CP_WAIT0()     asm volatile("cp.async.wait_group 0;" ::: "memory")
#define CP_WAIT1()     asm volatile("cp.async.wait_group 1;" ::: "memory")

// smem layout node GEMMs: A double buffer + B triple ring (staging reuses [0,34816))
#define SOF_A0 0
#define SOF_A1 16384
#define SOF_B  32768
#define SMEM_TG 81920
// edge GEMM: A tile + B; staging ALIASES A (A dead after mma)
#define EOF_A 0
#define EOF_B 32768
#define EOF_S 0                 // staging overlaps A: 128 rows x 80B = 10240
#define SMEM_TE 40960

// ---------------- weight preconversion ----------------
__global__ void k_conv_w(const float* __restrict__ Wemb, const float* __restrict__ Wnode,
                         const float* __restrict__ Wedge){
    int t = blockIdx.x * 256 + threadIdx.x;
    if (t < 16384){
        int n = t >> 7, kg = t & 127;
        int c = kg >> 6, k = kg & 63;
        float w = Wemb[(n >> 5) * 4096 + kg * 32 + (n & 31)];
        *(__half*)((char*)g_B1 + (uint32_t)c * 16384 + swoff64(n, k)) = __float2half_rn(w);
        return;
    }
    t -= 16384;
    if (t < 32768){
        int n = t >> 8, kg = t & 255;
        int c = kg >> 6, k = kg & 63;
        float w = Wnode[kg * 128 + n];
        if (kg >= 128) w *= 0.25f;
        *(__half*)((char*)g_B2 + (uint32_t)c * 16384 + swoff64(n, k)) = __float2half_rn(w);
        return;
    }
    t -= 32768;
    if (t < 16384){
        int q = t >> 12, r = t & 4095;
        int n = r >> 7, k = r & 127;
        float w = (k < 96) ? Wedge[q * 3072 + k * 32 + n] : 0.f;
        *(__half*)((char*)g_BE[q] + swoff256(n, k)) = __float2half_rn(w);
    }
}

// ---------------- single-pass fp16 MMA over one 64-K chunk (warp tile 32x32) ----------------
__device__ __forceinline__ void mma_chunk64(uint32_t Ab, uint32_t Bb,
                                            int warp_m, int warp_n, int lane, float acc[2][4][4]){
#pragma unroll
    for (int kc = 0; kc < 4; kc++){
        uint32_t a[2][4];
#pragma unroll
        for (int tf = 0; tf < 2; tf++){
            int row = warp_m * 32 + tf * 16 + (lane & 15);
            int ch = kc * 2 + (lane >> 4);
            uint32_t off = row * 128 + ((ch ^ (row & 7)) << 4);
            LDSM_X4(a[tf][0], a[tf][1], a[tf][2], a[tf][3], Ab + off);
        }
        uint32_t bfr[4][2];
#pragma unroll
        for (int jj = 0; jj < 2; jj++){
            int rowN = warp_n * 32 + jj * 16 + (lane & 7) + ((lane >> 4) << 3);
            int ch = kc * 2 + ((lane >> 3) & 1);
            uint32_t off = rowN * 128 + ((ch ^ (rowN & 7)) << 4);
            uint32_t r0, r1, r2, r3;
            LDSM_X4(r0, r1, r2, r3, Bb + off);
            bfr[jj*2][0] = r0;   bfr[jj*2][1] = r1;
            bfr[jj*2+1][0] = r2; bfr[jj*2+1][1] = r3;
        }
#pragma unroll
        for (int tf = 0; tf < 2; tf++)
#pragma unroll
            for (int j = 0; j < 4; j++)
                mma_f16(acc[tf][j], a[tf], bfr[j][0], bfr[j][1]);
    }
}

// fp32 regs -> fp16 swizzled smem A buffer
__device__ __forceinline__ void sts_a(char* smem, uint32_t abase, const float4 v[4], int m, int k16){
    uint4 H0, H1;
    H0.x = pk_h2(v[0].x, v[0].y); H0.y = pk_h2(v[0].z, v[0].w);
    H0.z = pk_h2(v[1].x, v[1].y); H0.w = pk_h2(v[1].z, v[1].w);
    H1.x = pk_h2(v[2].x, v[2].y); H1.y = pk_h2(v[2].z, v[2].w);
    H1.z = pk_h2(v[3].x, v[3].y); H1.w = pk_h2(v[3].z, v[3].w);
    *(uint4*)(smem + abase + swoff64(m, k16))     = H0;
    *(uint4*)(smem + abase + swoff64(m, k16 + 8)) = H1;
}
__device__ __forceinline__ void sts_a16(char* smem, uint32_t abase, const uint4 hv[2], int m, int k16){
    *(uint4*)(smem + abase + swoff64(m, k16))     = hv[0];
    *(uint4*)(smem + abase + swoff64(m, k16 + 8)) = hv[1];
}

__device__ __forceinline__ void cp_b(uint32_t sbuf, const char* src, int tid){
#pragma unroll
    for (int i = 0; i < 2; i++){
        uint32_t o = (uint32_t)(tid + 512 * i) * 16;
        CP16(sbuf + o, src + o);
    }
    CP_COMMIT();
}

// A-chunk loaders (thread: node row gm, 16 values at k16); gm<0 => zero
__device__ __forceinline__ void ldg_a_x(const float* __restrict__ x, int gm, int c, int k16, float4 v[4]){
    v[0] = v[1] = v[2] = v[3] = make_float4(0.f,0.f,0.f,0.f);
    if (gm >= 0){
        const float* src = x + (size_t)gm * 128 + c * 64 + k16;
        v[0] = *(const float4*)(src);
        v[1] = *(const float4*)(src + 4);
        v[2] = *(const float4*)(src + 8);
        v[3] = *(const float4*)(src + 12);
    }
}
__device__ __forceinline__ void ldg_a_agg16(int gm, int c, int k16, uint4 hv[2]){
    hv[0] = make_uint4(0u,0u,0u,0u); hv[1] = hv[0];
    if (gm >= 0){
        int d = (c - 2) * 2 + (k16 >> 5);
        int u = k16 & 31;
        int r = gm / WW, cc = gm - r * WW;
        int e = -1;
        if (d == 0){ if (r < HH-1) e = gm; }
        else if (d == 1){ if (cc >= 1) e = r*(WW-1) + cc - 1; }
        else if (d == 2){ if (r >= 1) e = gm - WW; }
        else            { if (cc <= WW-2) e = r*(WW-1) + cc; }
        if (e >= 0){
            const uint4* src = (const uint4*)(&g_EDGEH[d][0] + (size_t)e * 32 + u);
            hv[0] = src[0];
            hv[1] = src[1];
        }
    }
}

// ---------------- GEMM1: XQ(fp16) = relu(x @ Wcat), C=2, smem-staged epilogue ----------------
__global__ __launch_bounds__(512, 1) void k_tg1(const float* __restrict__ x){
    extern __shared__ char smem[];
    const uint32_t sb = smem_u32(smem);
    const int tid = threadIdx.x, wid = tid >> 5, lane = tid & 31;
    const int warp_m = wid >> 2, warp_n = wid & 3;
    const int M0 = blockIdx.x * 128;
    const int m = tid >> 2, k16 = (tid & 3) * 16;
    const int gm0 = (M0 + m < NN) ? (M0 + m) : -1;

    float acc[2][4][4];
#pragma unroll
    for (int t = 0; t < 2; t++)
#pragma unroll
        for (int j = 0; j < 4; j++)
#pragma unroll
            for (int e = 0; e < 4; e++) acc[t][j][e] = 0.f;

    float4 v[4];
    cp_b(sb + SOF_B, (const char*)g_B1, tid);
    ldg_a_x(x, gm0, 0, k16, v);

#pragma unroll
    for (int c = 0; c < 2; c++){
        uint32_t abase = (c & 1) ? SOF_A1 : SOF_A0;
        sts_a(smem, abase, v, m, k16);
        if (c == 0){
            cp_b(sb + SOF_B + 16384, (const char*)g_B1 + 16384, tid);
            ldg_a_x(x, gm0, 1, k16, v);
            CP_WAIT1();
        } else {
            CP_WAIT0();
        }
        __syncthreads();
        mma_chunk64(sb + abase, sb + SOF_B + (c % 3) * 16384, warp_m, warp_n, lane, acc);
    }
    // staged epilogue: fragments -> smem (272B rows) -> coalesced uint4 STG
    __syncthreads();
#pragma unroll
    for (int tf = 0; tf < 2; tf++){
        int r0 = warp_m * 32 + tf * 16 + (lane >> 2);
#pragma unroll
        for (int j = 0; j < 4; j++){
            int col = warp_n * 32 + j * 8 + (lane & 3) * 2;
            *(uint32_t*)(smem + r0 * 272 + col * 2) =
                pk_h2(fmaxf(acc[tf][j][0], 0.f), fmaxf(acc[tf][j][1], 0.f));
            *(uint32_t*)(smem + (r0 + 8) * 272 + col * 2) =
                pk_h2(fmaxf(acc[tf][j][2], 0.f), fmaxf(acc[tf][j][3], 0.f));
        }
    }
    __syncthreads();
#pragma unroll
    for (int i = 0; i < 4; i++){
        int idx = tid + 512 * i;
        int r = idx >> 4, c16 = idx & 15;
        if (M0 + r < NN)
            *(uint4*)(g_XQ + (size_t)(M0 + r) * 128 + c16 * 8) =
                *(const uint4*)(smem + r * 272 + c16 * 16);
    }
}

// ---------------- GEMM2 + fused pooling, full A-prefetch, C=4 chunks ----------------
__global__ __launch_bounds__(512, 1) void k_tg2(const float* __restrict__ x,
                                                float* __restrict__ out){
    extern __shared__ char smem[];
    const uint32_t sb = smem_u32(smem);
    const int tid = threadIdx.x, wid = tid >> 5, lane = tid & 31;
    const int warp_m = wid >> 2, warp_n = wid & 3;
    const int P0 = blockIdx.x * 32;      // 32 pooled cells per tile
    const int m = tid >> 2, k16 = (tid & 3) * 16;
    int gm0;
    {
        int cell = P0 + (m >> 2);
        int j = m & 3;
        gm0 = -1;
        if (cell < NP){
            int pr = cell / PCC, pc = cell - pr * PCC;
            int gr = 2 * pr + (j >> 1), gc = 2 * pc + (j & 1);
            if (gr < HH) gm0 = gr * WW + gc;
        }
    }

    float acc[2][4][4];
#pragma unroll
    for (int t = 0; t < 2; t++)
#pragma unroll
        for (int j = 0; j < 4; j++)
#pragma unroll
            for (int e = 0; e < 4; e++) acc[t][j][e] = 0.f;

    float4 v[4];
    uint4 hv2[2], hv3[2];
    cp_b(sb + SOF_B, (const char*)g_B2, tid);
    ldg_a_x(x, gm0, 0, k16, v);

    // c = 0: fill ch0, prefetch EVERYTHING else
    sts_a(smem, SOF_A0, v, m, k16);
    cp_b(sb + SOF_B + 16384, (const char*)g_B2 + 16384, tid);
    ldg_a_x(x, gm0, 1, k16, v);
    ldg_a_agg16(gm0, 2, k16, hv2);
    ldg_a_agg16(gm0, 3, k16, hv3);
    CP_WAIT1();
    __syncthreads();
    mma_chunk64(sb + SOF_A0, sb + SOF_B, warp_m, warp_n, lane, acc);
    // c = 1
    sts_a(smem, SOF_A1, v, m, k16);
    cp_b(sb + SOF_B + 32768, (const char*)g_B2 + 32768, tid);
    CP_WAIT1();
    __syncthreads();
    mma_chunk64(sb + SOF_A1, sb + SOF_B + 16384, warp_m, warp_n, lane, acc);
    // c = 2
    sts_a16(smem, SOF_A0, hv2, m, k16);
    cp_b(sb + SOF_B, (const char*)g_B2 + 49152, tid);
    CP_WAIT1();
    __syncthreads();
    mma_chunk64(sb + SOF_A0, sb + SOF_B + 32768, warp_m, warp_n, lane, acc);
    // c = 3
    sts_a16(smem, SOF_A1, hv3, m, k16);
    CP_WAIT0();
    __syncthreads();
    mma_chunk64(sb + SOF_A1, sb + SOF_B, warp_m, warp_n, lane, acc);

    // pooling epilogue: rows 4i..4i+3 = one pooled cell -> butterfly max -> direct store
#pragma unroll
    for (int tf = 0; tf < 2; tf++){
#pragma unroll
        for (int half = 0; half < 2; half++){
            int mloc = warp_m * 32 + tf * 16 + half * 8 + (lane >> 2);
#pragma unroll
            for (int jf = 0; jf < 4; jf++){
                float v0 = fmaxf(acc[tf][jf][half*2 + 0], 0.f);
                float v1 = fmaxf(acc[tf][jf][half*2 + 1], 0.f);
                v0 = fmaxf(v0, __shfl_xor_sync(0xffffffffu, v0, 4));
                v0 = fmaxf(v0, __shfl_xor_sync(0xffffffffu, v0, 8));
                v1 = fmaxf(v1, __shfl_xor_sync(0xffffffffu, v1, 4));
                v1 = fmaxf(v1, __shfl_xor_sync(0xffffffffu, v1, 8));
                if (((lane >> 2) & 3) == 0){
                    int p = P0 + (mloc >> 2);
                    if (p < NP){
                        int col = warp_n * 32 + jf * 8 + (lane & 3) * 2;
                        *(float2*)(out + (size_t)p * 128 + col) = make_float2(v0, v1);
                    }
                }
            }
        }
    }
}

// =====================================================================
// Edge GEMM: 128-edge tile, spread fill; staging aliases A tile
// =====================================================================
__global__ __launch_bounds__(256, 5) void k_edge(const float* __restrict__ efN,
                                                 const float* __restrict__ efE,
                                                 const float* __restrict__ efS,
                                                 const float* __restrict__ efW,
                                                 int unused){
    extern __shared__ char smem[];
    const uint32_t sb = smem_u32(smem);
    const int q = blockIdx.y;
    const float* ef = (q==0) ? efN : (q==1) ? efE : (q==2) ? efS : efW;
    const int E = (q==0 || q==2) ? E_NS : E_EW;
    const int M0 = blockIdx.x * 128;
    if (M0 >= E) return;
    const int tid = threadIdx.x, wid = tid >> 5, lane = tid & 31;

#pragma unroll
    for (int i = 0; i < 6; i++){
        int lin = tid + 256 * i;
        int m = lin / 12, k8c = lin - m * 12;
        int k8 = k8c * 8;
        int e = M0 + m;
        uint4 H = make_uint4(0u, 0u, 0u, 0u);
        if (e < E){
            if (k8c < 4){
                const float* src = ef + (size_t)e * 32 + k8;
                float4 v0 = *(const float4*)(src);
                float4 v1 = *(const float4*)(src + 4);
                H.x = pk_h2(v0.x, v0.y); H.y = pk_h2(v0.z, v0.w);
                H.z = pk_h2(v1.x, v1.y); H.w = pk_h2(v1.z, v1.w);
            } else {
                int s, t;
                if (q == 0){ s = e + WW; t = e; }
                else if (q == 2){ s = e; t = e + WW; }
                else { int r = e / (WW - 1); if (q == 1){ s = e + r; t = s + 1; } else { t = e + r; s = t + 1; } }
                int node = (k8c < 8) ? s : t;
                int u = (k8c & 3) * 8;
                H = *(const uint4*)(g_XQ + (size_t)node * 128 + q * 32 + u);
            }
        }
        *(uint4*)(smem + EOF_A + swoff256(m, k8)) = H;
    }
    {
        const uint4* bh = (const uint4*)g_BE[q];
#pragma unroll
        for (int i = 0; i < 2; i++){
            int idx = tid + 256 * i;
            ((uint4*)(smem + EOF_B))[idx] = bh[idx];
        }
    }
    __syncthreads();

    float acc[4][4];
#pragma unroll
    for (int j = 0; j < 4; j++)
#pragma unroll
        for (int e = 0; e < 4; e++) acc[j][e] = 0.f;

#pragma unroll
    for (int kc = 0; kc < 6; kc++){
        uint32_t a[4];
        {
            int row = wid * 16 + (lane & 15);
            int ch = kc * 2 + (lane >> 4);
            uint32_t off = row * 256 + ((ch ^ (row & 7)) << 4);
            LDSM_X4(a[0], a[1], a[2], a[3], sb + EOF_A + off);
        }
        uint32_t bfr[4][2];
#pragma unroll
        for (int jj = 0; jj < 2; jj++){
            int rowN = jj * 16 + (lane & 7) + ((lane >> 4) << 3);
            int ch = kc * 2 + ((lane >> 3) & 1);
            uint32_t off = rowN * 256 + ((ch ^ (rowN & 7)) << 4);
            uint32_t r0, r1, r2, r3;
            LDSM_X4(r0, r1, r2, r3, sb + EOF_B + off);
            bfr[jj*2][0] = r0;   bfr[jj*2][1] = r1;
            bfr[jj*2+1][0] = r2; bfr[jj*2+1][1] = r3;
        }
#pragma unroll
        for (int j = 0; j < 4; j++)
            mma_f16(acc[j], a, bfr[j][0], bfr[j][1]);
    }

    // staged epilogue into aliased A region (A dead after mma; barrier separates)
    __syncthreads();
    {
        int r0 = wid * 16 + (lane >> 2);
#pragma unroll
        for (int j = 0; j < 4; j++){
            int col = j * 8 + (lane & 3) * 2;
            *(uint32_t*)(smem + EOF_S + r0 * 80 + col * 2) =
                pk_h2(fmaxf(acc[j][0], 0.f), fmaxf(acc[j][1], 0.f));
            *(uint32_t*)(smem + EOF_S + (r0 + 8) * 80 + col * 2) =
                pk_h2(fmaxf(acc[j][2], 0.f), fmaxf(acc[j][3], 0.f));
        }
    }
    __syncthreads();
    {
        __half* ED = &g_EDGEH[q][0];
#pragma unroll
        for (int i = 0; i < 2; i++){
            int idx = tid + 256 * i;
            int r = idx >> 2, c = idx & 3;
            int e = M0 + r;
            if (e < E)
                *(uint4*)(ED + (size_t)e * 32 + c * 8) =
                    *(const uint4*)(smem + EOF_S + r * 80 + c * 16);
        }
    }
}

// ---------------- metadata / edge-feature kernels ----------------
__global__ void k_meta(float* __restrict__ out){
    int t = blockIdx.x * 256 + threadIdx.x;
    if (t < NP){
        out[OFF_POS + 2*t]     = (float)(t / PCC);
        out[OFF_POS + 2*t + 1] = (float)(t % PCC);
        return;
    }
    t -= NP;
    if (t < M_NS){
        int k = 1 + t / PCC, j = t % PCC;
        out[OFF_EIN + 2*t]     = (float)(k*PCC + j);
        out[OFF_EIN + 2*t + 1] = (float)((k-1)*PCC + j);
        return;
    }
    t -= M_NS;
    if (t < M_EW){
        int k = t / 217, j = t % 217;
        int s = k*PCC + j;
        out[OFF_EIE + 2*t]     = (float)s;
        out[OFF_EIE + 2*t + 1] = (float)(s + 1);
        return;
    }
    t -= M_EW;
    if (t < M_NS){
        int k = t / PCC, j = t % PCC;
        int s = k*PCC + j;
        out[OFF_EIS + 2*t]     = (float)s;
        out[OFF_EIS + 2*t + 1] = (float)(s + PCC);
        return;
    }
    t -= M_NS;
    if (t < M_EW){
        int k = t / 217, j = t % 217 + 1;
        int s = k*PCC + j;
        out[OFF_EIW + 2*t]     = (float)s;
        out[OFF_EIW + 2*t + 1] = (float)(s - 1);
        return;
    }
}

__global__ void k_efeat(float* __restrict__ out){
    const int d = blockIdx.y;
    const int M = (d == 0 || d == 2) ? M_NS : M_EW;
    int t = blockIdx.x * 256 + threadIdx.x;
    if (t >= M * 4) return;
    int m = t >> 2, fi = (t & 3) * 8;
    int e1, stride2 = 1; bool two = true; size_t off;
    if (d == 0){      int k = 1 + m/PCC, j = m%PCC; e1 = (2*k - 1)*WW + 2*j;      off = OFF_FN; }
    else if (d == 1){ int k = m/217,     j = m%217; e1 = 2*k*(WW-1) + 2*j + 1;    stride2 = WW-1; two = (k < 247); off = OFF_FE; }
    else if (d == 2){ int k = m/PCC,     j = m%PCC; e1 = (2*k + 1)*WW + 2*j;      off = OFF_FS; }
    else {            int k = m/217,     j = m%217 + 1; e1 = 2*k*(WW-1) + 2*j - 1; stride2 = WW-1; two = (k < 247); off = OFF_FW; }
    const __half* ED = &g_EDGEH[d][0];
    uint4 A = *(const uint4*)(ED + (size_t)e1*32 + fi);
    uint4 B = two ? *(const uint4*)(ED + (size_t)(e1 + stride2)*32 + fi) : make_uint4(0u,0u,0u,0u);
    float* o = out + off + (size_t)m*32 + fi;
    const uint32_t* aw = &A.x;
    const uint32_t* bw = &B.x;
#pragma unroll
    for (int w = 0; w < 4; w++){
        float2 fa = __half22float2(*(const __half2*)&aw[w]);
        float2 fb = __half22float2(*(const __half2*)&bw[w]);
        o[2*w]   = fmaxf(fa.x, fb.x);
        o[2*w+1] = fmaxf(fa.y, fb.y);
    }
}

// =====================================================================
extern "C" void kernel_launch(void* const* d_in, const int* in_sizes, int n_in,
                              void* d_out, int out_size){
    const float* x     = (const float*)d_in[0];
    const float* efN   = (const float*)d_in[6];
    const float* efE   = (const float*)d_in[7];
    const float* efS   = (const float*)d_in[8];
    const float* efW   = (const float*)d_in[9];
    const float* Wemb  = (const float*)d_in[10];
    const float* Wedge = (const float*)d_in[11];
    const float* Wnode = (const float*)d_in[12];
    float* out = (float*)d_out;

    static bool attr_done = false;
    if (!attr_done){
        cudaFuncSetAttribute(k_tg1, cudaFuncAttributeMaxDynamicSharedMemorySize, SMEM_TG);
        cudaFuncSetAttribute(k_tg2, cudaFuncAttributeMaxDynamicSharedMemorySize, SMEM_TG);
        cudaFuncSetAttribute(k_edge, cudaFuncAttributeMaxDynamicSharedMemorySize, SMEM_TE);
        attr_done = true;
    }

    const int gm = (NN + 127) / 128;             // 1687 tiles
    const int gp = (NP + 31) / 32;               // 1690 pooled tiles
    k_conv_w<<<(65536 + 255)/256, 256>>>(Wemb, Wnode, Wedge);
    k_tg1<<<gm, 512, SMEM_TG>>>(x);
    dim3 ge((E_NS + 127) / 128, 4);
    k_edge<<<ge, 256, SMEM_TE>>>(efN, efE, efS, efW, 0);
    k_tg2<<<gp, 512, SMEM_TG>>>(x, out);

    const int metaT = NP + 2*M_NS + 2*M_EW;
    dim3 gf((M_NS*4 + 255) / 256, 4);
    k_meta<<<(metaT + 255)/256, 256>>>(out);
    k_efeat<<<gf, 256>>>(out);
}